// round 9
// baseline (speedup 1.0000x reference)
#include <cuda_runtime.h>
#include <cuda_bf16.h>
#include <stdint.h>
#include <math.h>

#define D_MODEL 1024
#define N_HEAD  16
#define D_H     64
#define BATCH   4
#define LQ      1024
#define LK      2048

// ---------------------------------------------------------------------------
// Scratch (no cudaMalloc allowed)
// ---------------------------------------------------------------------------
__device__ __nv_bfloat16 g_qinh[(size_t)BATCH * LQ * D_MODEL];
__device__ __nv_bfloat16 g_qinl[(size_t)BATCH * LQ * D_MODEL];
__device__ __nv_bfloat16 g_ckinh[(size_t)BATCH * LK * D_MODEL];  // compacted kv input
__device__ __nv_bfloat16 g_ckinl[(size_t)BATCH * LK * D_MODEL];
__device__ __nv_bfloat16 g_wqh[(size_t)D_MODEL * D_MODEL];
__device__ __nv_bfloat16 g_wql[(size_t)D_MODEL * D_MODEL];
__device__ __nv_bfloat16 g_wkh[(size_t)D_MODEL * D_MODEL];
__device__ __nv_bfloat16 g_wkl[(size_t)D_MODEL * D_MODEL];
__device__ __nv_bfloat16 g_wvh[(size_t)D_MODEL * D_MODEL];
__device__ __nv_bfloat16 g_wvl[(size_t)D_MODEL * D_MODEL];
__device__ __nv_bfloat16 g_woh[(size_t)D_MODEL * D_MODEL];
__device__ __nv_bfloat16 g_wol[(size_t)D_MODEL * D_MODEL];
__device__ __nv_bfloat16 g_qh[(size_t)BATCH * LQ * D_MODEL];
__device__ __nv_bfloat16 g_ql[(size_t)BATCH * LQ * D_MODEL];
__device__ __nv_bfloat16 g_kh[(size_t)BATCH * LK * D_MODEL];
__device__ __nv_bfloat16 g_kl[(size_t)BATCH * LK * D_MODEL];
__device__ __nv_bfloat16 g_vh[(size_t)BATCH * LK * D_MODEL];
__device__ __nv_bfloat16 g_vl[(size_t)BATCH * LK * D_MODEL];
__device__ __nv_bfloat16 g_ah[(size_t)BATCH * LQ * D_MODEL];
__device__ __nv_bfloat16 g_al[(size_t)BATCH * LQ * D_MODEL];
// compaction metadata
__device__ int   g_kidx[(size_t)BATCH * LK];
__device__ int   g_nkv[BATCH];
__device__ int   g_npad[BATCH];
__device__ float g_biasc[(size_t)BATCH * LK];

// ---------------------------------------------------------------------------
// Helpers
// ---------------------------------------------------------------------------
__device__ __forceinline__ uint32_t smem_u32(const void* p) {
    uint32_t a;
    asm("{ .reg .u64 t; cvta.to.shared.u64 t, %1; cvt.u32.u64 %0, t; }"
        : "=r"(a) : "l"(p));
    return a;
}
__device__ __forceinline__ void cp16(uint32_t d, const void* g) {
    asm volatile("cp.async.cg.shared.global [%0], [%1], 16;" :: "r"(d), "l"(g));
}
__device__ __forceinline__ void cp_commit() {
    asm volatile("cp.async.commit_group;" ::: "memory");
}
__device__ __forceinline__ void ldm_x4(uint32_t* r, uint32_t addr) {
    asm volatile("ldmatrix.sync.aligned.m8n8.x4.shared.b16 {%0,%1,%2,%3}, [%4];"
                 : "=r"(r[0]), "=r"(r[1]), "=r"(r[2]), "=r"(r[3]) : "r"(addr));
}
__device__ __forceinline__ void ldm_x4_trans(uint32_t* r, uint32_t addr) {
    asm volatile("ldmatrix.sync.aligned.m8n8.x4.trans.shared.b16 {%0,%1,%2,%3}, [%4];"
                 : "=r"(r[0]), "=r"(r[1]), "=r"(r[2]), "=r"(r[3]) : "r"(addr));
}
__device__ __forceinline__ void mma_bf16(float* c, const uint32_t* a, const uint32_t* b) {
    asm volatile(
        "mma.sync.aligned.m16n8k16.row.col.f32.bf16.bf16.f32 "
        "{%0,%1,%2,%3}, {%4,%5,%6,%7}, {%8,%9}, {%0,%1,%2,%3};"
        : "+f"(c[0]), "+f"(c[1]), "+f"(c[2]), "+f"(c[3])
        : "r"(a[0]), "r"(a[1]), "r"(a[2]), "r"(a[3]), "r"(b[0]), "r"(b[1]));
}
__device__ __forceinline__ void split2(float a, float b, uint32_t& hi, uint32_t& lo) {
    __nv_bfloat162 h2 = __float22bfloat162_rn(make_float2(a, b));
    float2 hf = __bfloat1622float2(h2);
    __nv_bfloat162 l2 = __float22bfloat162_rn(make_float2(a - hf.x, b - hf.y));
    hi = *reinterpret_cast<uint32_t*>(&h2);
    lo = *reinterpret_cast<uint32_t*>(&l2);
}

// ---------------------------------------------------------------------------
// Fused pre-split: q_input + all 4 weights in one launch (range dispatch).
// blocks [0,4096): q_in; [4096,8192): weights (1024 blocks each).
// ---------------------------------------------------------------------------
__global__ __launch_bounds__(256) void split_all_kernel(
    const float* __restrict__ q_in,
    const float* __restrict__ WQ, const float* __restrict__ WK,
    const float* __restrict__ WV, const float* __restrict__ WO)
{
    const int blk = blockIdx.x;
    const float* src;
    __nv_bfloat16 *dh, *dl;
    int base;
    if (blk < 4096) {
        src = q_in; dh = g_qinh; dl = g_qinl; base = blk;
    } else {
        const int w = (blk - 4096) >> 10;
        base = (blk - 4096) & 1023;
        switch (w) {
            case 0:  src = WQ; dh = g_wqh; dl = g_wql; break;
            case 1:  src = WK; dh = g_wkh; dl = g_wkl; break;
            case 2:  src = WV; dh = g_wvh; dl = g_wvl; break;
            default: src = WO; dh = g_woh; dl = g_wol; break;
        }
    }
    const int i = base * 256 + threadIdx.x;
    float4 v = reinterpret_cast<const float4*>(src)[i];
    uint32_t h0, l0, h1, l1;
    split2(v.x, v.y, h0, l0);
    split2(v.z, v.w, h1, l1);
    reinterpret_cast<uint2*>(dh)[i] = make_uint2(h0, h1);
    reinterpret_cast<uint2*>(dl)[i] = make_uint2(l0, l1);
}

// ---------------------------------------------------------------------------
// Compaction scan: 1 block/batch, 1024 threads, 2 keys each.
// ---------------------------------------------------------------------------
__global__ __launch_bounds__(1024) void compact_scan_kernel(const int* __restrict__ mask)
{
    __shared__ int ssum[1024];
    const int b = blockIdx.x, t = threadIdx.x;
    const int* m = mask + (size_t)b * LK;
    const int f0 = (m[2 * t]     == 0) ? 1 : 0;
    const int f1 = (m[2 * t + 1] == 0) ? 1 : 0;
    ssum[t] = f0 + f1;
    __syncthreads();
    for (int off = 1; off < 1024; off <<= 1) {
        const int v = (t >= off) ? ssum[t - off] : 0;
        __syncthreads();
        ssum[t] += v;
        __syncthreads();
    }
    const int excl = ssum[t] - f0 - f1;
    if (f0) g_kidx[(size_t)b * LK + excl]      = 2 * t;
    if (f1) g_kidx[(size_t)b * LK + excl + f0] = 2 * t + 1;
    const int n = ssum[1023];
    if (t == 0) {
        g_nkv[b]  = n;
        g_npad[b] = (n + 127) & ~127;
    }
    g_biasc[(size_t)b * LK + 2 * t]     = (2 * t     < n) ? 0.0f : -1.0e30f;
    g_biasc[(size_t)b * LK + 2 * t + 1] = (2 * t + 1 < n) ? 0.0f : -1.0e30f;
}

// ---------------------------------------------------------------------------
// Fused gather + split: read f32 kv_input rows via kidx, write compact
// split-bf16 (pads zeroed). grid (LK/8, BATCH), 256 threads.
// ---------------------------------------------------------------------------
__global__ __launch_bounds__(256) void gather_split_kernel(const float* __restrict__ kv_in)
{
    const int b  = blockIdx.y;
    const int j0 = blockIdx.x * 8;
    const int n = g_nkv[b], npad = g_npad[b];
    if (j0 >= npad) return;
    const int tid = threadIdx.x;
    for (int i = tid; i < 8 * 256; i += 256) {
        const int r = i >> 8, c = i & 255;          // c: float4 index within row
        const int j = j0 + r;
        if (j >= npad) continue;
        uint2 uh = make_uint2(0, 0), ul = make_uint2(0, 0);
        if (j < n) {
            const int src = g_kidx[(size_t)b * LK + j];
            float4 v = reinterpret_cast<const float4*>(kv_in)
                           [((size_t)b * LK + src) * 256 + c];
            uint32_t h0, l0, h1, l1;
            split2(v.x, v.y, h0, l0);
            split2(v.z, v.w, h1, l1);
            uh = make_uint2(h0, h1);
            ul = make_uint2(l0, l1);
        }
        const size_t dof = ((size_t)b * LK + j) * 256 + c;
        reinterpret_cast<uint2*>(g_ckinh)[dof] = uh;
        reinterpret_cast<uint2*>(g_ckinl)[dof] = ul;
    }
}

// ---------------------------------------------------------------------------
// GEMM core: 128x128 tile, BK=32, 256 thr, 4-stage cp.async, fragment reuse.
// K = N = D_MODEL fixed.
// ---------------------------------------------------------------------------
#define G_STG 37888   // Ah 10240 + Al 10240 + Bh 8704 + Bl 8704
#define GDSM  (4 * G_STG)

__device__ __forceinline__ void gemm_core(
    const __nv_bfloat16* __restrict__ Ahg, const __nv_bfloat16* __restrict__ Alg,
    const __nv_bfloat16* __restrict__ Whg, const __nv_bfloat16* __restrict__ Wlg,
    int brow, int bcol, char* dsm, float acc[4][4][4])
{
    const uint32_t sb = smem_u32(dsm);
    const int tid  = threadIdx.x;
    const int warp = tid >> 5, lane = tid & 31;
    const int wm   = warp >> 2, wn = warp & 3;

#pragma unroll
    for (int mi = 0; mi < 4; mi++)
#pragma unroll
        for (int ni = 0; ni < 4; ni++)
#pragma unroll
            for (int r = 0; r < 4; r++) acc[mi][ni][r] = 0.0f;

    auto issue = [&](int kt, int s) {
        const int k0 = kt * 32;
        const uint32_t st = sb + s * G_STG;
#pragma unroll
        for (int i = 0; i < 2; i++) {
            const int idx = i * 256 + tid;
            const int r = idx >> 2, c = idx & 3;
            const uint32_t d = st + r * 80 + c * 16;
            const size_t go = (size_t)(brow + r) * D_MODEL + k0 + c * 8;
            cp16(d,         Ahg + go);
            cp16(d + 10240, Alg + go);
        }
#pragma unroll
        for (int i = 0; i < 2; i++) {
            const int idx = i * 256 + tid;
            const int r = idx >> 4, c = idx & 15;
            const uint32_t d = st + 20480 + r * 272 + c * 16;
            const size_t go = (size_t)(k0 + r) * D_MODEL + bcol + c * 8;
            cp16(d,        Whg + go);
            cp16(d + 8704, Wlg + go);
        }
        cp_commit();
    };

    const int NK = D_MODEL / 32;
    issue(0, 0);
    issue(1, 1);
    for (int kt = 0; kt < NK; kt++) {
        if (kt + 2 < NK) {
            issue(kt + 2, (kt + 2) & 3);
            asm volatile("cp.async.wait_group 2;" ::: "memory");
        } else if (kt + 1 < NK) {
            asm volatile("cp.async.wait_group 1;" ::: "memory");
        } else {
            asm volatile("cp.async.wait_group 0;" ::: "memory");
        }
        __syncthreads();

        const uint32_t ah = sb + (kt & 3) * G_STG;
        const uint32_t al = ah + 10240;
        const uint32_t bh = ah + 20480;
        const uint32_t bl = ah + 29184;

#pragma unroll
        for (int ks = 0; ks < 2; ks++) {
            uint32_t afh[4][4], afl[4][4], bfh[2][4], bfl[2][4];
#pragma unroll
            for (int mi = 0; mi < 4; mi++) {
                const int row = wm * 64 + mi * 16 + (lane & 15);
                const int col = ks * 16 + (lane >> 4) * 8;
                const uint32_t off = (uint32_t)(row * 40 + col) * 2;
                ldm_x4(afh[mi], ah + off);
                ldm_x4(afl[mi], al + off);
            }
#pragma unroll
            for (int np = 0; np < 2; np++) {
                const int krow = ks * 16 + (lane & 15);
                const int ncol = wn * 32 + np * 16 + ((lane >> 4) & 1) * 8;
                const uint32_t off = (uint32_t)(krow * 136 + ncol) * 2;
                ldm_x4_trans(bfh[np], bh + off);
                ldm_x4_trans(bfl[np], bl + off);
            }
#pragma unroll
            for (int mi = 0; mi < 4; mi++)
#pragma unroll
                for (int ni = 0; ni < 4; ni++) {
                    uint32_t* ph = &bfh[ni >> 1][(ni & 1) * 2];
                    uint32_t* pl = &bfl[ni >> 1][(ni & 1) * 2];
                    mma_bf16(acc[mi][ni], afh[mi], ph);
                    mma_bf16(acc[mi][ni], afh[mi], pl);
                    mma_bf16(acc[mi][ni], afl[mi], ph);
                }
        }
    }
}

// ---------------------------------------------------------------------------
// Fused Q + K + V projection GEMM. grid (16, 96):
//   y <  32: Q rows (bx<8 valid), out g_qh/g_ql scaled by 0.125
//   y >= 32: compacted KV rows (early-exit past npad); bx<8 -> K else V
// ---------------------------------------------------------------------------
__global__ __launch_bounds__(256) void gemm_qkv(
    const float* __restrict__ bQ, const float* __restrict__ bK,
    const float* __restrict__ bV)
{
    extern __shared__ __align__(16) char dsm[];

    const __nv_bfloat16 *Ahg, *Alg, *Whg, *Wlg;
    const float* bias;
    __nv_bfloat16 *Ch, *Cl;
    float scale;
    int brow, bx = blockIdx.x;

    if (blockIdx.y < 32) {
        if (bx >= 8) return;
        Ahg = g_qinh; Alg = g_qinl; Whg = g_wqh; Wlg = g_wql;
        bias = bQ; Ch = g_qh; Cl = g_ql; scale = 0.125f;
        brow = blockIdx.y * 128;
    } else {
        brow = (blockIdx.y - 32) * 128;
        const int bb = brow / LK;
        if ((brow % LK) >= g_npad[bb]) return;
        Ahg = g_ckinh; Alg = g_ckinl; scale = 1.0f;
        if (bx < 8) { Whg = g_wkh; Wlg = g_wkl; bias = bK; Ch = g_kh; Cl = g_kl; }
        else { bx -= 8; Whg = g_wvh; Wlg = g_wvl; bias = bV; Ch = g_vh; Cl = g_vl; }
    }
    const int bcol = bx * 128;

    float acc[4][4][4];
    gemm_core(Ahg, Alg, Whg, Wlg, brow, bcol, dsm, acc);

    const int lane = threadIdx.x & 31, warp = threadIdx.x >> 5;
    const int wm = warp >> 2, wn = warp & 3;
    const int g = lane >> 2, t4 = lane & 3;
#pragma unroll
    for (int mi = 0; mi < 4; mi++) {
        const int row = brow + wm * 64 + mi * 16 + g;
#pragma unroll
        for (int ni = 0; ni < 4; ni++) {
            const int col = bcol + wn * 32 + ni * 8 + 2 * t4;
            const float b0 = bias[col], b1 = bias[col + 1];
            uint32_t h0, l0, h1, l1;
            split2((acc[mi][ni][0] + b0) * scale, (acc[mi][ni][1] + b1) * scale, h0, l0);
            split2((acc[mi][ni][2] + b0) * scale, (acc[mi][ni][3] + b1) * scale, h1, l1);
            *reinterpret_cast<uint32_t*>(&Ch[(size_t)row * D_MODEL + col])       = h0;
            *reinterpret_cast<uint32_t*>(&Cl[(size_t)row * D_MODEL + col])       = l0;
            *reinterpret_cast<uint32_t*>(&Ch[(size_t)(row + 8) * D_MODEL + col]) = h1;
            *reinterpret_cast<uint32_t*>(&Cl[(size_t)(row + 8) * D_MODEL + col]) = l1;
        }
    }
}

// Output projection: fp32 out to d_out.
__global__ __launch_bounds__(256) void gemm_o(
    const float* __restrict__ bO, float* __restrict__ C)
{
    extern __shared__ __align__(16) char dsm[];
    const int brow = blockIdx.y * 128;
    const int bcol = blockIdx.x * 128;

    float acc[4][4][4];
    gemm_core(g_ah, g_al, g_woh, g_wol, brow, bcol, dsm, acc);

    const int lane = threadIdx.x & 31, warp = threadIdx.x >> 5;
    const int wm = warp >> 2, wn = warp & 3;
    const int g = lane >> 2, t4 = lane & 3;
#pragma unroll
    for (int mi = 0; mi < 4; mi++) {
        const int row = brow + wm * 64 + mi * 16 + g;
#pragma unroll
        for (int ni = 0; ni < 4; ni++) {
            const int col = bcol + wn * 32 + ni * 8 + 2 * t4;
            const float b0 = bO[col], b1 = bO[col + 1];
            *reinterpret_cast<float2*>(C + (size_t)row * D_MODEL + col) =
                make_float2(acc[mi][ni][0] + b0, acc[mi][ni][1] + b1);
            *reinterpret_cast<float2*>(C + (size_t)(row + 8) * D_MODEL + col) =
                make_float2(acc[mi][ni][2] + b0, acc[mi][ni][3] + b1);
        }
    }
}

// ---------------------------------------------------------------------------
// Tensor-core flash attention over compacted keys (npad[b]/64 tiles).
// QT=64, 128 threads / 4 warps, 2 CTAs/SM, 2-stage cp.async pipeline.
// ---------------------------------------------------------------------------
#define A_TS   9216
#define A_STG  (4 * A_TS)
#define A_BOFF (2 * A_STG)
#define A_DSM  (A_BOFF + 512)

__global__ __launch_bounds__(128, 2) void attn_mma()
{
    extern __shared__ __align__(16) char dsm[];
    const uint32_t sb = smem_u32(dsm);

    const int tid  = threadIdx.x;
    const int warp = tid >> 5, lane = tid & 31;
    const int g    = lane >> 2, t4 = lane & 3;
    const int q0   = blockIdx.x * 64;
    const int h    = blockIdx.y;
    const int b    = blockIdx.z;
    const int NK   = g_npad[b] / 64;

    // ---- Q fragments via stage-0 area ----
    uint32_t qfh[4][4], qfl[4][4];
    {
        const size_t qbase = ((size_t)b * LQ + q0) * D_MODEL + h * D_H;
#pragma unroll
        for (int i = 0; i < 4; i++) {
            const int idx = i * 128 + tid;
            const int r = idx >> 3, c = idx & 7;
            const size_t go = qbase + (size_t)r * D_MODEL + c * 8;
            *reinterpret_cast<uint4*>(dsm + r * 144 + c * 16) =
                *reinterpret_cast<const uint4*>(g_qh + go);
            *reinterpret_cast<uint4*>(dsm + A_TS + r * 144 + c * 16) =
                *reinterpret_cast<const uint4*>(g_ql + go);
        }
        __syncthreads();
        const int rbase = warp * 16;
#pragma unroll
        for (int s = 0; s < 4; s++) {
            const uint32_t off =
                (uint32_t)((rbase + (lane & 15)) * 72 + (lane >> 4) * 8 + s * 16) * 2;
            ldm_x4(qfh[s], sb + off);
            ldm_x4(qfl[s], sb + A_TS + off);
        }
        __syncthreads();
    }

    auto issue = [&](int kt, int s) {
        const size_t kvbase = ((size_t)b * LK + kt * 64) * D_MODEL + h * D_H;
        const uint32_t st = sb + s * A_STG;
#pragma unroll
        for (int i = 0; i < 16; i++) {
            const int tile = i >> 2;
            const int idx = (i & 3) * 128 + tid;
            const int r = idx >> 3, c = idx & 7;
            const size_t go = kvbase + (size_t)r * D_MODEL + c * 8;
            const uint32_t d = st + tile * A_TS + r * 144 + c * 16;
            const __nv_bfloat16* src =
                tile == 0 ? g_kh : tile == 1 ? g_kl : tile == 2 ? g_vh : g_vl;
            cp16(d, src + go);
        }
        if (tid < 16)
            cp16(sb + A_BOFF + s * 256 + tid * 16,
                 g_biasc + (size_t)b * LK + kt * 64 + tid * 4);
        cp_commit();
    };

    float m0 = -1.0e30f, m1 = -1.0e30f, l0 = 0.0f, l1 = 0.0f;
    float o[8][4];
#pragma unroll
    for (int j = 0; j < 8; j++)
#pragma unroll
        for (int r = 0; r < 4; r++) o[j][r] = 0.0f;

    issue(0, 0);
    for (int kt = 0; kt < NK; kt++) {
        const int st = kt & 1;
        if (kt + 1 < NK) {
            issue(kt + 1, st ^ 1);
            asm volatile("cp.async.wait_group 1;" ::: "memory");
        } else {
            asm volatile("cp.async.wait_group 0;" ::: "memory");
        }
        __syncthreads();

        const uint32_t khb = sb + st * A_STG;
        const uint32_t klb = khb + A_TS;
        const uint32_t vhb = khb + 2 * A_TS;
        const uint32_t vlb = khb + 3 * A_TS;
        const float* bias_s = reinterpret_cast<const float*>(dsm + A_BOFF + st * 256);

        // ---- S = Q K^T (3-pass split) ----
        float s[8][4];
#pragma unroll
        for (int j = 0; j < 8; j++)
#pragma unroll
            for (int r = 0; r < 4; r++) s[j][r] = 0.0f;

#pragma unroll
        for (int ks = 0; ks < 4; ks++) {
#pragma unroll
            for (int jp = 0; jp < 4; jp++) {
                const int row = jp * 16 + ((lane >> 4) & 1) * 8 + (lane & 7);
                const int col = ks * 16 + ((lane >> 3) & 1) * 8;
                const uint32_t off = (uint32_t)(row * 72 + col) * 2;
                uint32_t kh4[4], kl4[4];
                ldm_x4(kh4, khb + off);
                ldm_x4(kl4, klb + off);
                mma_bf16(s[2 * jp],     qfh[ks], kh4);
                mma_bf16(s[2 * jp],     qfl[ks], kh4);
                mma_bf16(s[2 * jp],     qfh[ks], kl4);
                mma_bf16(s[2 * jp + 1], qfh[ks], kh4 + 2);
                mma_bf16(s[2 * jp + 1], qfl[ks], kh4 + 2);
                mma_bf16(s[2 * jp + 1], qfh[ks], kl4 + 2);
            }
        }

        // ---- pad bias + online softmax ----
        float mx0 = -1.0e30f, mx1 = -1.0e30f;
#pragma unroll
        for (int j = 0; j < 8; j++) {
            const float b0 = bias_s[j * 8 + 2 * t4];
            const float b1 = bias_s[j * 8 + 2 * t4 + 1];
            s[j][0] += b0; s[j][1] += b1;
            s[j][2] += b0; s[j][3] += b1;
            mx0 = fmaxf(mx0, fmaxf(s[j][0], s[j][1]));
            mx1 = fmaxf(mx1, fmaxf(s[j][2], s[j][3]));
        }
        mx0 = fmaxf(mx0, __shfl_xor_sync(0xffffffffu, mx0, 1));
        mx0 = fmaxf(mx0, __shfl_xor_sync(0xffffffffu, mx0, 2));
        mx1 = fmaxf(mx1, __shfl_xor_sync(0xffffffffu, mx1, 1));
        mx1 = fmaxf(mx1, __shfl_xor_sync(0xffffffffu, mx1, 2));

        const float m0n = fmaxf(m0, mx0), m1n = fmaxf(m1, mx1);
        const float c0 = __expf(m0 - m0n), c1 = __expf(m1 - m1n);
        m0 = m0n; m1 = m1n;

        float sum0 = 0.0f, sum1 = 0.0f;
#pragma unroll
        for (int j = 0; j < 8; j++) {
            s[j][0] = __expf(s[j][0] - m0n);
            s[j][1] = __expf(s[j][1] - m0n);
            s[j][2] = __expf(s[j][2] - m1n);
            s[j][3] = __expf(s[j][3] - m1n);
            sum0 += s[j][0] + s[j][1];
            sum1 += s[j][2] + s[j][3];
        }
        sum0 += __shfl_xor_sync(0xffffffffu, sum0, 1);
        sum0 += __shfl_xor_sync(0xffffffffu, sum0, 2);
        sum1 += __shfl_xor_sync(0xffffffffu, sum1, 1);
        sum1 += __shfl_xor_sync(0xffffffffu, sum1, 2);
        l0 = l0 * c0 + sum0;
        l1 = l1 * c1 + sum1;

#pragma unroll
        for (int j = 0; j < 8; j++) {
            o[j][0] *= c0; o[j][1] *= c0;
            o[j][2] *= c1; o[j][3] *= c1;
        }

        // ---- O += P V (3-pass split) ----
#pragma unroll
        for (int ks = 0; ks < 4; ks++) {
            uint32_t pah[4], pal[4];
            split2(s[2 * ks][0],     s[2 * ks][1],     pah[0], pal[0]);
            split2(s[2 * ks][2],     s[2 * ks][3],     pah[1], pal[1]);
            split2(s[2 * ks + 1][0], s[2 * ks + 1][1], pah[2], pal[2]);
            split2(s[2 * ks + 1][2], s[2 * ks + 1][3], pah[3], pal[3]);
#pragma unroll
            for (int jp = 0; jp < 4; jp++) {
                const int row = ks * 16 + (lane & 15);
                const int col = jp * 16 + ((lane >> 4) & 1) * 8;
                const uint32_t off = (uint32_t)(row * 72 + col) * 2;
                uint32_t vh4[4], vl4[4];
                ldm_x4_trans(vh4, vhb + off);
                ldm_x4_trans(vl4, vlb + off);
                mma_bf16(o[2 * jp],     pah, vh4);
                mma_bf16(o[2 * jp],     pal, vh4);
                mma_bf16(o[2 * jp],     pah, vl4);
                mma_bf16(o[2 * jp + 1], pah, vh4 + 2);
                mma_bf16(o[2 * jp + 1], pal, vh4 + 2);
                mma_bf16(o[2 * jp + 1], pah, vl4 + 2);
            }
        }
        __syncthreads();
    }

    // ---- normalize + write split-bf16 output ----
    const float li0 = 1.0f / l0, li1 = 1.0f / l1;
    const int row0 = q0 + warp * 16 + g;
    const size_t base0 = ((size_t)b * LQ + row0) * D_MODEL + h * D_H;
    const size_t base1 = base0 + (size_t)8 * D_MODEL;
#pragma unroll
    for (int j = 0; j < 8; j++) {
        const int col = j * 8 + 2 * t4;
        uint32_t h0, l0r, h1, l1r;
        split2(o[j][0] * li0, o[j][1] * li0, h0, l0r);
        split2(o[j][2] * li1, o[j][3] * li1, h1, l1r);
        *reinterpret_cast<uint32_t*>(&g_ah[base0 + col]) = h0;
        *reinterpret_cast<uint32_t*>(&g_al[base0 + col]) = l0r;
        *reinterpret_cast<uint32_t*>(&g_ah[base1 + col]) = h1;
        *reinterpret_cast<uint32_t*>(&g_al[base1 + col]) = l1r;
    }
}

// ---------------------------------------------------------------------------
// Launch
// ---------------------------------------------------------------------------
extern "C" void kernel_launch(void* const* d_in, const int* in_sizes, int n_in,
                              void* d_out, int out_size)
{
    const float* q_in  = (const float*)d_in[0];
    const float* kv_in = (const float*)d_in[1];
    const int*   mask  = (const int*)  d_in[2];
    const float* W_Q   = (const float*)d_in[3];
    const float* b_Q   = (const float*)d_in[4];
    const float* W_K   = (const float*)d_in[5];
    const float* b_K   = (const float*)d_in[6];
    const float* W_V   = (const float*)d_in[7];
    const float* b_V   = (const float*)d_in[8];
    const float* W_O   = (const float*)d_in[9];
    const float* b_O   = (const float*)d_in[10];

    cudaFuncSetAttribute(gemm_qkv, cudaFuncAttributeMaxDynamicSharedMemorySize, GDSM);
    cudaFuncSetAttribute(gemm_o,   cudaFuncAttributeMaxDynamicSharedMemorySize, GDSM);
    cudaFuncSetAttribute(attn_mma, cudaFuncAttributeMaxDynamicSharedMemorySize, A_DSM);

    // ---- preprocessing: splits + compaction ----
    split_all_kernel<<<8192, 256>>>(q_in, W_Q, W_K, W_V, W_O);
    compact_scan_kernel<<<BATCH, 1024>>>(mask);
    gather_split_kernel<<<dim3(LK / 8, BATCH), 256>>>(kv_in);

    // ---- fused Q/K/V projections ----
    gemm_qkv<<<dim3(16, 96), 256, GDSM>>>(b_Q, b_K, b_V);

    // ---- attention over compacted keys ----
    attn_mma<<<dim3(LQ / 64, N_HEAD, BATCH), 128, A_DSM>>>();

    // ---- output projection ----
    gemm_o<<<dim3(8, 32), 256, GDSM>>>(b_O, (float*)d_out);
}

// round 10
// speedup vs baseline: 1.0213x; 1.0213x over previous
#include <cuda_runtime.h>
#include <cuda_bf16.h>
#include <stdint.h>
#include <math.h>

#define D_MODEL 1024
#define N_HEAD  16
#define D_H     64
#define BATCH   4
#define LQ      1024
#define LK      2048

// ---------------------------------------------------------------------------
// Scratch (no cudaMalloc allowed)
// ---------------------------------------------------------------------------
__device__ __nv_bfloat16 g_qinh[(size_t)BATCH * LQ * D_MODEL];
__device__ __nv_bfloat16 g_qinl[(size_t)BATCH * LQ * D_MODEL];
__device__ __nv_bfloat16 g_ckinh[(size_t)BATCH * LK * D_MODEL];  // compacted kv input
__device__ __nv_bfloat16 g_ckinl[(size_t)BATCH * LK * D_MODEL];
__device__ __nv_bfloat16 g_wqh[(size_t)D_MODEL * D_MODEL];
__device__ __nv_bfloat16 g_wql[(size_t)D_MODEL * D_MODEL];
__device__ __nv_bfloat16 g_wkh[(size_t)D_MODEL * D_MODEL];
__device__ __nv_bfloat16 g_wkl[(size_t)D_MODEL * D_MODEL];
__device__ __nv_bfloat16 g_wvh[(size_t)D_MODEL * D_MODEL];
__device__ __nv_bfloat16 g_wvl[(size_t)D_MODEL * D_MODEL];
__device__ __nv_bfloat16 g_woh[(size_t)D_MODEL * D_MODEL];
__device__ __nv_bfloat16 g_wol[(size_t)D_MODEL * D_MODEL];
__device__ __nv_bfloat16 g_qh[(size_t)BATCH * LQ * D_MODEL];
__device__ __nv_bfloat16 g_ql[(size_t)BATCH * LQ * D_MODEL];
__device__ __nv_bfloat16 g_kh[(size_t)BATCH * LK * D_MODEL];
__device__ __nv_bfloat16 g_kl[(size_t)BATCH * LK * D_MODEL];
__device__ __nv_bfloat16 g_vh[(size_t)BATCH * LK * D_MODEL];
__device__ __nv_bfloat16 g_vl[(size_t)BATCH * LK * D_MODEL];
__device__ __nv_bfloat16 g_ah[(size_t)BATCH * LQ * D_MODEL];
__device__ __nv_bfloat16 g_al[(size_t)BATCH * LQ * D_MODEL];
// compaction metadata
__device__ int   g_kidx[(size_t)BATCH * LK];
__device__ int   g_nkv[BATCH];
__device__ int   g_npad[BATCH];
__device__ float g_biasc[(size_t)BATCH * LK];

// ---------------------------------------------------------------------------
// Helpers
// ---------------------------------------------------------------------------
__device__ __forceinline__ uint32_t smem_u32(const void* p) {
    uint32_t a;
    asm("{ .reg .u64 t; cvta.to.shared.u64 t, %1; cvt.u32.u64 %0, t; }"
        : "=r"(a) : "l"(p));
    return a;
}
__device__ __forceinline__ void cp16(uint32_t d, const void* g) {
    asm volatile("cp.async.cg.shared.global [%0], [%1], 16;" :: "r"(d), "l"(g));
}
__device__ __forceinline__ void cp_commit() {
    asm volatile("cp.async.commit_group;" ::: "memory");
}
__device__ __forceinline__ void ldm_x4(uint32_t* r, uint32_t addr) {
    asm volatile("ldmatrix.sync.aligned.m8n8.x4.shared.b16 {%0,%1,%2,%3}, [%4];"
                 : "=r"(r[0]), "=r"(r[1]), "=r"(r[2]), "=r"(r[3]) : "r"(addr));
}
__device__ __forceinline__ void ldm_x4_trans(uint32_t* r, uint32_t addr) {
    asm volatile("ldmatrix.sync.aligned.m8n8.x4.trans.shared.b16 {%0,%1,%2,%3}, [%4];"
                 : "=r"(r[0]), "=r"(r[1]), "=r"(r[2]), "=r"(r[3]) : "r"(addr));
}
__device__ __forceinline__ void mma_bf16(float* c, const uint32_t* a, const uint32_t* b) {
    asm volatile(
        "mma.sync.aligned.m16n8k16.row.col.f32.bf16.bf16.f32 "
        "{%0,%1,%2,%3}, {%4,%5,%6,%7}, {%8,%9}, {%0,%1,%2,%3};"
        : "+f"(c[0]), "+f"(c[1]), "+f"(c[2]), "+f"(c[3])
        : "r"(a[0]), "r"(a[1]), "r"(a[2]), "r"(a[3]), "r"(b[0]), "r"(b[1]));
}
__device__ __forceinline__ void split2(float a, float b, uint32_t& hi, uint32_t& lo) {
    __nv_bfloat162 h2 = __float22bfloat162_rn(make_float2(a, b));
    float2 hf = __bfloat1622float2(h2);
    __nv_bfloat162 l2 = __float22bfloat162_rn(make_float2(a - hf.x, b - hf.y));
    hi = *reinterpret_cast<uint32_t*>(&h2);
    lo = *reinterpret_cast<uint32_t*>(&l2);
}

// ---------------------------------------------------------------------------
// Fused pre-split: q_input + all 4 weights in one launch (range dispatch).
// ---------------------------------------------------------------------------
__global__ __launch_bounds__(256) void split_all_kernel(
    const float* __restrict__ q_in,
    const float* __restrict__ WQ, const float* __restrict__ WK,
    const float* __restrict__ WV, const float* __restrict__ WO)
{
    const int blk = blockIdx.x;
    const float* src;
    __nv_bfloat16 *dh, *dl;
    int base;
    if (blk < 4096) {
        src = q_in; dh = g_qinh; dl = g_qinl; base = blk;
    } else {
        const int w = (blk - 4096) >> 10;
        base = (blk - 4096) & 1023;
        switch (w) {
            case 0:  src = WQ; dh = g_wqh; dl = g_wql; break;
            case 1:  src = WK; dh = g_wkh; dl = g_wkl; break;
            case 2:  src = WV; dh = g_wvh; dl = g_wvl; break;
            default: src = WO; dh = g_woh; dl = g_wol; break;
        }
    }
    const int i = base * 256 + threadIdx.x;
    float4 v = reinterpret_cast<const float4*>(src)[i];
    uint32_t h0, l0, h1, l1;
    split2(v.x, v.y, h0, l0);
    split2(v.z, v.w, h1, l1);
    reinterpret_cast<uint2*>(dh)[i] = make_uint2(h0, h1);
    reinterpret_cast<uint2*>(dl)[i] = make_uint2(l0, l1);
}

// ---------------------------------------------------------------------------
// Compaction scan: 1 block/batch, 1024 threads, 2 keys each.
// ---------------------------------------------------------------------------
__global__ __launch_bounds__(1024) void compact_scan_kernel(const int* __restrict__ mask)
{
    __shared__ int ssum[1024];
    const int b = blockIdx.x, t = threadIdx.x;
    const int* m = mask + (size_t)b * LK;
    const int f0 = (m[2 * t]     == 0) ? 1 : 0;
    const int f1 = (m[2 * t + 1] == 0) ? 1 : 0;
    ssum[t] = f0 + f1;
    __syncthreads();
    for (int off = 1; off < 1024; off <<= 1) {
        const int v = (t >= off) ? ssum[t - off] : 0;
        __syncthreads();
        ssum[t] += v;
        __syncthreads();
    }
    const int excl = ssum[t] - f0 - f1;
    if (f0) g_kidx[(size_t)b * LK + excl]      = 2 * t;
    if (f1) g_kidx[(size_t)b * LK + excl + f0] = 2 * t + 1;
    const int n = ssum[1023];
    if (t == 0) {
        g_nkv[b]  = n;
        g_npad[b] = (n + 127) & ~127;
    }
    g_biasc[(size_t)b * LK + 2 * t]     = (2 * t     < n) ? 0.0f : -1.0e30f;
    g_biasc[(size_t)b * LK + 2 * t + 1] = (2 * t + 1 < n) ? 0.0f : -1.0e30f;
}

// ---------------------------------------------------------------------------
// Fused gather + split: f32 kv_input rows -> compact split-bf16 (pads zeroed).
// ---------------------------------------------------------------------------
__global__ __launch_bounds__(256) void gather_split_kernel(const float* __restrict__ kv_in)
{
    const int b  = blockIdx.y;
    const int j0 = blockIdx.x * 8;
    const int n = g_nkv[b], npad = g_npad[b];
    if (j0 >= npad) return;
    const int tid = threadIdx.x;
    for (int i = tid; i < 8 * 256; i += 256) {
        const int r = i >> 8, c = i & 255;
        const int j = j0 + r;
        if (j >= npad) continue;
        uint2 uh = make_uint2(0, 0), ul = make_uint2(0, 0);
        if (j < n) {
            const int src = g_kidx[(size_t)b * LK + j];
            float4 v = reinterpret_cast<const float4*>(kv_in)
                           [((size_t)b * LK + src) * 256 + c];
            uint32_t h0, l0, h1, l1;
            split2(v.x, v.y, h0, l0);
            split2(v.z, v.w, h1, l1);
            uh = make_uint2(h0, h1);
            ul = make_uint2(l0, l1);
        }
        const size_t dof = ((size_t)b * LK + j) * 256 + c;
        reinterpret_cast<uint2*>(g_ckinh)[dof] = uh;
        reinterpret_cast<uint2*>(g_ckinl)[dof] = ul;
    }
}

// ---------------------------------------------------------------------------
// GEMM core: 128x128 tile, BK=32, 256 thr, 2-stage cp.async, fragment reuse.
// 2 CTAs/SM (smem 75776 * 2 = 151552 < 227KB) for cross-CTA latency hiding.
// ---------------------------------------------------------------------------
#define G_STG 37888   // Ah 10240 + Al 10240 + Bh 8704 + Bl 8704
#define GDSM  (2 * G_STG)

__device__ __forceinline__ void gemm_core(
    const __nv_bfloat16* __restrict__ Ahg, const __nv_bfloat16* __restrict__ Alg,
    const __nv_bfloat16* __restrict__ Whg, const __nv_bfloat16* __restrict__ Wlg,
    int brow, int bcol, char* dsm, float acc[4][4][4])
{
    const uint32_t sb = smem_u32(dsm);
    const int tid  = threadIdx.x;
    const int warp = tid >> 5, lane = tid & 31;
    const int wm   = warp >> 2, wn = warp & 3;

#pragma unroll
    for (int mi = 0; mi < 4; mi++)
#pragma unroll
        for (int ni = 0; ni < 4; ni++)
#pragma unroll
            for (int r = 0; r < 4; r++) acc[mi][ni][r] = 0.0f;

    auto issue = [&](int kt, int s) {
        const int k0 = kt * 32;
        const uint32_t st = sb + s * G_STG;
#pragma unroll
        for (int i = 0; i < 2; i++) {
            const int idx = i * 256 + tid;
            const int r = idx >> 2, c = idx & 3;
            const uint32_t d = st + r * 80 + c * 16;
            const size_t go = (size_t)(brow + r) * D_MODEL + k0 + c * 8;
            cp16(d,         Ahg + go);
            cp16(d + 10240, Alg + go);
        }
#pragma unroll
        for (int i = 0; i < 2; i++) {
            const int idx = i * 256 + tid;
            const int r = idx >> 4, c = idx & 15;
            const uint32_t d = st + 20480 + r * 272 + c * 16;
            const size_t go = (size_t)(k0 + r) * D_MODEL + bcol + c * 8;
            cp16(d,        Whg + go);
            cp16(d + 8704, Wlg + go);
        }
        cp_commit();
    };

    const int NK = D_MODEL / 32;
    issue(0, 0);
    for (int kt = 0; kt < NK; kt++) {
        const int s = kt & 1;
        if (kt + 1 < NK) {
            issue(kt + 1, s ^ 1);
            asm volatile("cp.async.wait_group 1;" ::: "memory");
        } else {
            asm volatile("cp.async.wait_group 0;" ::: "memory");
        }
        __syncthreads();

        const uint32_t ah = sb + s * G_STG;
        const uint32_t al = ah + 10240;
        const uint32_t bh = ah + 20480;
        const uint32_t bl = ah + 29184;

#pragma unroll
        for (int ks = 0; ks < 2; ks++) {
            uint32_t afh[4][4], afl[4][4], bfh[2][4], bfl[2][4];
#pragma unroll
            for (int mi = 0; mi < 4; mi++) {
                const int row = wm * 64 + mi * 16 + (lane & 15);
                const int col = ks * 16 + (lane >> 4) * 8;
                const uint32_t off = (uint32_t)(row * 40 + col) * 2;
                ldm_x4(afh[mi], ah + off);
                ldm_x4(afl[mi], al + off);
            }
#pragma unroll
            for (int np = 0; np < 2; np++) {
                const int krow = ks * 16 + (lane & 15);
                const int ncol = wn * 32 + np * 16 + ((lane >> 4) & 1) * 8;
                const uint32_t off = (uint32_t)(krow * 136 + ncol) * 2;
                ldm_x4_trans(bfh[np], bh + off);
                ldm_x4_trans(bfl[np], bl + off);
            }
#pragma unroll
            for (int mi = 0; mi < 4; mi++)
#pragma unroll
                for (int ni = 0; ni < 4; ni++) {
                    uint32_t* ph = &bfh[ni >> 1][(ni & 1) * 2];
                    uint32_t* pl = &bfl[ni >> 1][(ni & 1) * 2];
                    mma_bf16(acc[mi][ni], afh[mi], ph);
                    mma_bf16(acc[mi][ni], afh[mi], pl);
                    mma_bf16(acc[mi][ni], afl[mi], ph);
                }
        }
        __syncthreads();
    }
}

// ---------------------------------------------------------------------------
// Fused Q + K + V projection GEMM. grid (16, 96).
// ---------------------------------------------------------------------------
__global__ __launch_bounds__(256, 2) void gemm_qkv(
    const float* __restrict__ bQ, const float* __restrict__ bK,
    const float* __restrict__ bV)
{
    extern __shared__ __align__(16) char dsm[];

    const __nv_bfloat16 *Ahg, *Alg, *Whg, *Wlg;
    const float* bias;
    __nv_bfloat16 *Ch, *Cl;
    float scale;
    int brow, bx = blockIdx.x;

    if (blockIdx.y < 32) {
        if (bx >= 8) return;
        Ahg = g_qinh; Alg = g_qinl; Whg = g_wqh; Wlg = g_wql;
        bias = bQ; Ch = g_qh; Cl = g_ql; scale = 0.125f;
        brow = blockIdx.y * 128;
    } else {
        brow = (blockIdx.y - 32) * 128;
        const int bb = brow / LK;
        if ((brow % LK) >= g_npad[bb]) return;
        Ahg = g_ckinh; Alg = g_ckinl; scale = 1.0f;
        if (bx < 8) { Whg = g_wkh; Wlg = g_wkl; bias = bK; Ch = g_kh; Cl = g_kl; }
        else { bx -= 8; Whg = g_wvh; Wlg = g_wvl; bias = bV; Ch = g_vh; Cl = g_vl; }
    }
    const int bcol = bx * 128;

    float acc[4][4][4];
    gemm_core(Ahg, Alg, Whg, Wlg, brow, bcol, dsm, acc);

    const int lane = threadIdx.x & 31, warp = threadIdx.x >> 5;
    const int wm = warp >> 2, wn = warp & 3;
    const int g = lane >> 2, t4 = lane & 3;
#pragma unroll
    for (int mi = 0; mi < 4; mi++) {
        const int row = brow + wm * 64 + mi * 16 + g;
#pragma unroll
        for (int ni = 0; ni < 4; ni++) {
            const int col = bcol + wn * 32 + ni * 8 + 2 * t4;
            const float b0 = bias[col], b1 = bias[col + 1];
            uint32_t h0, l0, h1, l1;
            split2((acc[mi][ni][0] + b0) * scale, (acc[mi][ni][1] + b1) * scale, h0, l0);
            split2((acc[mi][ni][2] + b0) * scale, (acc[mi][ni][3] + b1) * scale, h1, l1);
            *reinterpret_cast<uint32_t*>(&Ch[(size_t)row * D_MODEL + col])       = h0;
            *reinterpret_cast<uint32_t*>(&Cl[(size_t)row * D_MODEL + col])       = l0;
            *reinterpret_cast<uint32_t*>(&Ch[(size_t)(row + 8) * D_MODEL + col]) = h1;
            *reinterpret_cast<uint32_t*>(&Cl[(size_t)(row + 8) * D_MODEL + col]) = l1;
        }
    }
}

// Output projection: fp32 out to d_out.
__global__ __launch_bounds__(256, 2) void gemm_o(
    const float* __restrict__ bO, float* __restrict__ C)
{
    extern __shared__ __align__(16) char dsm[];
    const int brow = blockIdx.y * 128;
    const int bcol = blockIdx.x * 128;

    float acc[4][4][4];
    gemm_core(g_ah, g_al, g_woh, g_wol, brow, bcol, dsm, acc);

    const int lane = threadIdx.x & 31, warp = threadIdx.x >> 5;
    const int wm = warp >> 2, wn = warp & 3;
    const int g = lane >> 2, t4 = lane & 3;
#pragma unroll
    for (int mi = 0; mi < 4; mi++) {
        const int row = brow + wm * 64 + mi * 16 + g;
#pragma unroll
        for (int ni = 0; ni < 4; ni++) {
            const int col = bcol + wn * 32 + ni * 8 + 2 * t4;
            const float b0 = bO[col], b1 = bO[col + 1];
            *reinterpret_cast<float2*>(C + (size_t)row * D_MODEL + col) =
                make_float2(acc[mi][ni][0] + b0, acc[mi][ni][1] + b1);
            *reinterpret_cast<float2*>(C + (size_t)(row + 8) * D_MODEL + col) =
                make_float2(acc[mi][ni][2] + b0, acc[mi][ni][3] + b1);
        }
    }
}

// ---------------------------------------------------------------------------
// Tensor-core flash attention over compacted keys (npad[b]/64 tiles).
// QT=64, 128 threads / 4 warps, 2 CTAs/SM, 2-stage cp.async pipeline.
// ---------------------------------------------------------------------------
#define A_TS   9216
#define A_STG  (4 * A_TS)
#define A_BOFF (2 * A_STG)
#define A_DSM  (A_BOFF + 512)

__global__ __launch_bounds__(128, 2) void attn_mma()
{
    extern __shared__ __align__(16) char dsm[];
    const uint32_t sb = smem_u32(dsm);

    const int tid  = threadIdx.x;
    const int warp = tid >> 5, lane = tid & 31;
    const int g    = lane >> 2, t4 = lane & 3;
    const int q0   = blockIdx.x * 64;
    const int h    = blockIdx.y;
    const int b    = blockIdx.z;
    const int NK   = g_npad[b] / 64;

    // ---- Q fragments via stage-0 area ----
    uint32_t qfh[4][4], qfl[4][4];
    {
        const size_t qbase = ((size_t)b * LQ + q0) * D_MODEL + h * D_H;
#pragma unroll
        for (int i = 0; i < 4; i++) {
            const int idx = i * 128 + tid;
            const int r = idx >> 3, c = idx & 7;
            const size_t go = qbase + (size_t)r * D_MODEL + c * 8;
            *reinterpret_cast<uint4*>(dsm + r * 144 + c * 16) =
                *reinterpret_cast<const uint4*>(g_qh + go);
            *reinterpret_cast<uint4*>(dsm + A_TS + r * 144 + c * 16) =
                *reinterpret_cast<const uint4*>(g_ql + go);
        }
        __syncthreads();
        const int rbase = warp * 16;
#pragma unroll
        for (int s = 0; s < 4; s++) {
            const uint32_t off =
                (uint32_t)((rbase + (lane & 15)) * 72 + (lane >> 4) * 8 + s * 16) * 2;
            ldm_x4(qfh[s], sb + off);
            ldm_x4(qfl[s], sb + A_TS + off);
        }
        __syncthreads();
    }

    auto issue = [&](int kt, int s) {
        const size_t kvbase = ((size_t)b * LK + kt * 64) * D_MODEL + h * D_H;
        const uint32_t st = sb + s * A_STG;
#pragma unroll
        for (int i = 0; i < 16; i++) {
            const int tile = i >> 2;
            const int idx = (i & 3) * 128 + tid;
            const int r = idx >> 3, c = idx & 7;
            const size_t go = kvbase + (size_t)r * D_MODEL + c * 8;
            const uint32_t d = st + tile * A_TS + r * 144 + c * 16;
            const __nv_bfloat16* src =
                tile == 0 ? g_kh : tile == 1 ? g_kl : tile == 2 ? g_vh : g_vl;
            cp16(d, src + go);
        }
        if (tid < 16)
            cp16(sb + A_BOFF + s * 256 + tid * 16,
                 g_biasc + (size_t)b * LK + kt * 64 + tid * 4);
        cp_commit();
    };

    float m0 = -1.0e30f, m1 = -1.0e30f, l0 = 0.0f, l1 = 0.0f;
    float o[8][4];
#pragma unroll
    for (int j = 0; j < 8; j++)
#pragma unroll
        for (int r = 0; r < 4; r++) o[j][r] = 0.0f;

    issue(0, 0);
    for (int kt = 0; kt < NK; kt++) {
        const int st = kt & 1;
        if (kt + 1 < NK) {
            issue(kt + 1, st ^ 1);
            asm volatile("cp.async.wait_group 1;" ::: "memory");
        } else {
            asm volatile("cp.async.wait_group 0;" ::: "memory");
        }
        __syncthreads();

        const uint32_t khb = sb + st * A_STG;
        const uint32_t klb = khb + A_TS;
        const uint32_t vhb = khb + 2 * A_TS;
        const uint32_t vlb = khb + 3 * A_TS;
        const float* bias_s = reinterpret_cast<const float*>(dsm + A_BOFF + st * 256);

        // ---- S = Q K^T (3-pass split) ----
        float s[8][4];
#pragma unroll
        for (int j = 0; j < 8; j++)
#pragma unroll
            for (int r = 0; r < 4; r++) s[j][r] = 0.0f;

#pragma unroll
        for (int ks = 0; ks < 4; ks++) {
#pragma unroll
            for (int jp = 0; jp < 4; jp++) {
                const int row = jp * 16 + ((lane >> 4) & 1) * 8 + (lane & 7);
                const int col = ks * 16 + ((lane >> 3) & 1) * 8;
                const uint32_t off = (uint32_t)(row * 72 + col) * 2;
                uint32_t kh4[4], kl4[4];
                ldm_x4(kh4, khb + off);
                ldm_x4(kl4, klb + off);
                mma_bf16(s[2 * jp],     qfh[ks], kh4);
                mma_bf16(s[2 * jp],     qfl[ks], kh4);
                mma_bf16(s[2 * jp],     qfh[ks], kl4);
                mma_bf16(s[2 * jp + 1], qfh[ks], kh4 + 2);
                mma_bf16(s[2 * jp + 1], qfl[ks], kh4 + 2);
                mma_bf16(s[2 * jp + 1], qfh[ks], kl4 + 2);
            }
        }

        // ---- pad bias + online softmax ----
        float mx0 = -1.0e30f, mx1 = -1.0e30f;
#pragma unroll
        for (int j = 0; j < 8; j++) {
            const float b0 = bias_s[j * 8 + 2 * t4];
            const float b1 = bias_s[j * 8 + 2 * t4 + 1];
            s[j][0] += b0; s[j][1] += b1;
            s[j][2] += b0; s[j][3] += b1;
            mx0 = fmaxf(mx0, fmaxf(s[j][0], s[j][1]));
            mx1 = fmaxf(mx1, fmaxf(s[j][2], s[j][3]));
        }
        mx0 = fmaxf(mx0, __shfl_xor_sync(0xffffffffu, mx0, 1));
        mx0 = fmaxf(mx0, __shfl_xor_sync(0xffffffffu, mx0, 2));
        mx1 = fmaxf(mx1, __shfl_xor_sync(0xffffffffu, mx1, 1));
        mx1 = fmaxf(mx1, __shfl_xor_sync(0xffffffffu, mx1, 2));

        const float m0n = fmaxf(m0, mx0), m1n = fmaxf(m1, mx1);
        const float c0 = __expf(m0 - m0n), c1 = __expf(m1 - m1n);
        m0 = m0n; m1 = m1n;

        float sum0 = 0.0f, sum1 = 0.0f;
#pragma unroll
        for (int j = 0; j < 8; j++) {
            s[j][0] = __expf(s[j][0] - m0n);
            s[j][1] = __expf(s[j][1] - m0n);
            s[j][2] = __expf(s[j][2] - m1n);
            s[j][3] = __expf(s[j][3] - m1n);
            sum0 += s[j][0] + s[j][1];
            sum1 += s[j][2] + s[j][3];
        }
        sum0 += __shfl_xor_sync(0xffffffffu, sum0, 1);
        sum0 += __shfl_xor_sync(0xffffffffu, sum0, 2);
        sum1 += __shfl_xor_sync(0xffffffffu, sum1, 1);
        sum1 += __shfl_xor_sync(0xffffffffu, sum1, 2);
        l0 = l0 * c0 + sum0;
        l1 = l1 * c1 + sum1;

#pragma unroll
        for (int j = 0; j < 8; j++) {
            o[j][0] *= c0; o[j][1] *= c0;
            o[j][2] *= c1; o[j][3] *= c1;
        }

        // ---- O += P V (3-pass split) ----
#pragma unroll
        for (int ks = 0; ks < 4; ks++) {
            uint32_t pah[4], pal[4];
            split2(s[2 * ks][0],     s[2 * ks][1],     pah[0], pal[0]);
            split2(s[2 * ks][2],     s[2 * ks][3],     pah[1], pal[1]);
            split2(s[2 * ks + 1][0], s[2 * ks + 1][1], pah[2], pal[2]);
            split2(s[2 * ks + 1][2], s[2 * ks + 1][3], pah[3], pal[3]);
#pragma unroll
            for (int jp = 0; jp < 4; jp++) {
                const int row = ks * 16 + (lane & 15);
                const int col = jp * 16 + ((lane >> 4) & 1) * 8;
                const uint32_t off = (uint32_t)(row * 72 + col) * 2;
                uint32_t vh4[4], vl4[4];
                ldm_x4_trans(vh4, vhb + off);
                ldm_x4_trans(vl4, vlb + off);
                mma_bf16(o[2 * jp],     pah, vh4);
                mma_bf16(o[2 * jp],     pal, vh4);
                mma_bf16(o[2 * jp],     pah, vl4);
                mma_bf16(o[2 * jp + 1], pah, vh4 + 2);
                mma_bf16(o[2 * jp + 1], pal, vh4 + 2);
                mma_bf16(o[2 * jp + 1], pah, vl4 + 2);
            }
        }
        __syncthreads();
    }

    // ---- normalize + write split-bf16 output ----
    const float li0 = 1.0f / l0, li1 = 1.0f / l1;
    const int row0 = q0 + warp * 16 + g;
    const size_t base0 = ((size_t)b * LQ + row0) * D_MODEL + h * D_H;
    const size_t base1 = base0 + (size_t)8 * D_MODEL;
#pragma unroll
    for (int j = 0; j < 8; j++) {
        const int col = j * 8 + 2 * t4;
        uint32_t h0, l0r, h1, l1r;
        split2(o[j][0] * li0, o[j][1] * li0, h0, l0r);
        split2(o[j][2] * li1, o[j][3] * li1, h1, l1r);
        *reinterpret_cast<uint32_t*>(&g_ah[base0 + col]) = h0;
        *reinterpret_cast<uint32_t*>(&g_al[base0 + col]) = l0r;
        *reinterpret_cast<uint32_t*>(&g_ah[base1 + col]) = h1;
        *reinterpret_cast<uint32_t*>(&g_al[base1 + col]) = l1r;
    }
}

// ---------------------------------------------------------------------------
// Launch
// ---------------------------------------------------------------------------
extern "C" void kernel_launch(void* const* d_in, const int* in_sizes, int n_in,
                              void* d_out, int out_size)
{
    const float* q_in  = (const float*)d_in[0];
    const float* kv_in = (const float*)d_in[1];
    const int*   mask  = (const int*)  d_in[2];
    const float* W_Q   = (const float*)d_in[3];
    const float* b_Q   = (const float*)d_in[4];
    const float* W_K   = (const float*)d_in[5];
    const float* b_K   = (const float*)d_in[6];
    const float* W_V   = (const float*)d_in[7];
    const float* b_V   = (const float*)d_in[8];
    const float* W_O   = (const float*)d_in[9];
    const float* b_O   = (const float*)d_in[10];

    cudaFuncSetAttribute(gemm_qkv, cudaFuncAttributeMaxDynamicSharedMemorySize, GDSM);
    cudaFuncSetAttribute(gemm_o,   cudaFuncAttributeMaxDynamicSharedMemorySize, GDSM);
    cudaFuncSetAttribute(attn_mma, cudaFuncAttributeMaxDynamicSharedMemorySize, A_DSM);

    // ---- preprocessing: splits + compaction ----
    split_all_kernel<<<8192, 256>>>(q_in, W_Q, W_K, W_V, W_O);
    compact_scan_kernel<<<BATCH, 1024>>>(mask);
    gather_split_kernel<<<dim3(LK / 8, BATCH), 256>>>(kv_in);

    // ---- fused Q/K/V projections ----
    gemm_qkv<<<dim3(16, 96), 256, GDSM>>>(b_Q, b_K, b_V);

    // ---- attention over compacted keys ----
    attn_mma<<<dim3(LQ / 64, N_HEAD, BATCH), 128, A_DSM>>>();

    // ---- output projection ----
    gemm_o<<<dim3(8, 32), 256, GDSM>>>(b_O, (float*)d_out);
}

// round 11
// speedup vs baseline: 1.0240x; 1.0026x over previous
#include <cuda_runtime.h>
#include <cuda_bf16.h>
#include <stdint.h>
#include <math.h>

#define D_MODEL 1024
#define N_HEAD  16
#define D_H     64
#define BATCH   4
#define LQ      1024
#define LK      2048

// ---------------------------------------------------------------------------
// Scratch (no cudaMalloc allowed)
// ---------------------------------------------------------------------------
__device__ __nv_bfloat16 g_qinh[(size_t)BATCH * LQ * D_MODEL];
__device__ __nv_bfloat16 g_qinl[(size_t)BATCH * LQ * D_MODEL];
__device__ __nv_bfloat16 g_ckinh[(size_t)BATCH * LK * D_MODEL];  // compacted kv input
__device__ __nv_bfloat16 g_ckinl[(size_t)BATCH * LK * D_MODEL];
__device__ __nv_bfloat16 g_wqh[(size_t)D_MODEL * D_MODEL];
__device__ __nv_bfloat16 g_wql[(size_t)D_MODEL * D_MODEL];
__device__ __nv_bfloat16 g_wkh[(size_t)D_MODEL * D_MODEL];
__device__ __nv_bfloat16 g_wkl[(size_t)D_MODEL * D_MODEL];
__device__ __nv_bfloat16 g_wvh[(size_t)D_MODEL * D_MODEL];
__device__ __nv_bfloat16 g_wvl[(size_t)D_MODEL * D_MODEL];
__device__ __nv_bfloat16 g_woh[(size_t)D_MODEL * D_MODEL];
__device__ __nv_bfloat16 g_wol[(size_t)D_MODEL * D_MODEL];
__device__ __nv_bfloat16 g_qh[(size_t)BATCH * LQ * D_MODEL];
__device__ __nv_bfloat16 g_ql[(size_t)BATCH * LQ * D_MODEL];
__device__ __nv_bfloat16 g_kh[(size_t)BATCH * LK * D_MODEL];
__device__ __nv_bfloat16 g_kl[(size_t)BATCH * LK * D_MODEL];
__device__ __nv_bfloat16 g_vh[(size_t)BATCH * LK * D_MODEL];
__device__ __nv_bfloat16 g_vl[(size_t)BATCH * LK * D_MODEL];
__device__ __nv_bfloat16 g_ah[(size_t)BATCH * LQ * D_MODEL];
__device__ __nv_bfloat16 g_al[(size_t)BATCH * LQ * D_MODEL];
// compaction metadata
__device__ int   g_kidx[(size_t)BATCH * LK];
__device__ int   g_nkv[BATCH];
__device__ int   g_npad[BATCH];
__device__ float g_biasc[(size_t)BATCH * LK];

// ---------------------------------------------------------------------------
// Helpers
// ---------------------------------------------------------------------------
__device__ __forceinline__ uint32_t smem_u32(const void* p) {
    uint32_t a;
    asm("{ .reg .u64 t; cvta.to.shared.u64 t, %1; cvt.u32.u64 %0, t; }"
        : "=r"(a) : "l"(p));
    return a;
}
__device__ __forceinline__ void cp16(uint32_t d, const void* g) {
    asm volatile("cp.async.cg.shared.global [%0], [%1], 16;" :: "r"(d), "l"(g));
}
__device__ __forceinline__ void cp_commit() {
    asm volatile("cp.async.commit_group;" ::: "memory");
}
__device__ __forceinline__ void ldm_x4(uint32_t* r, uint32_t addr) {
    asm volatile("ldmatrix.sync.aligned.m8n8.x4.shared.b16 {%0,%1,%2,%3}, [%4];"
                 : "=r"(r[0]), "=r"(r[1]), "=r"(r[2]), "=r"(r[3]) : "r"(addr));
}
__device__ __forceinline__ void ldm_x4_trans(uint32_t* r, uint32_t addr) {
    asm volatile("ldmatrix.sync.aligned.m8n8.x4.trans.shared.b16 {%0,%1,%2,%3}, [%4];"
                 : "=r"(r[0]), "=r"(r[1]), "=r"(r[2]), "=r"(r[3]) : "r"(addr));
}
__device__ __forceinline__ void mma_bf16(float* c, const uint32_t* a, const uint32_t* b) {
    asm volatile(
        "mma.sync.aligned.m16n8k16.row.col.f32.bf16.bf16.f32 "
        "{%0,%1,%2,%3}, {%4,%5,%6,%7}, {%8,%9}, {%0,%1,%2,%3};"
        : "+f"(c[0]), "+f"(c[1]), "+f"(c[2]), "+f"(c[3])
        : "r"(a[0]), "r"(a[1]), "r"(a[2]), "r"(a[3]), "r"(b[0]), "r"(b[1]));
}
__device__ __forceinline__ void split2(float a, float b, uint32_t& hi, uint32_t& lo) {
    __nv_bfloat162 h2 = __float22bfloat162_rn(make_float2(a, b));
    float2 hf = __bfloat1622float2(h2);
    __nv_bfloat162 l2 = __float22bfloat162_rn(make_float2(a - hf.x, b - hf.y));
    hi = *reinterpret_cast<uint32_t*>(&h2);
    lo = *reinterpret_cast<uint32_t*>(&l2);
}

// ---------------------------------------------------------------------------
// Fused pre-split: q_input + all 4 weights in one launch (range dispatch).
// ---------------------------------------------------------------------------
__global__ __launch_bounds__(256) void split_all_kernel(
    const float* __restrict__ q_in,
    const float* __restrict__ WQ, const float* __restrict__ WK,
    const float* __restrict__ WV, const float* __restrict__ WO)
{
    const int blk = blockIdx.x;
    const float* src;
    __nv_bfloat16 *dh, *dl;
    int base;
    if (blk < 4096) {
        src = q_in; dh = g_qinh; dl = g_qinl; base = blk;
    } else {
        const int w = (blk - 4096) >> 10;
        base = (blk - 4096) & 1023;
        switch (w) {
            case 0:  src = WQ; dh = g_wqh; dl = g_wql; break;
            case 1:  src = WK; dh = g_wkh; dl = g_wkl; break;
            case 2:  src = WV; dh = g_wvh; dl = g_wvl; break;
            default: src = WO; dh = g_woh; dl = g_wol; break;
        }
    }
    const int i = base * 256 + threadIdx.x;
    float4 v = reinterpret_cast<const float4*>(src)[i];
    uint32_t h0, l0, h1, l1;
    split2(v.x, v.y, h0, l0);
    split2(v.z, v.w, h1, l1);
    reinterpret_cast<uint2*>(dh)[i] = make_uint2(h0, h1);
    reinterpret_cast<uint2*>(dl)[i] = make_uint2(l0, l1);
}

// ---------------------------------------------------------------------------
// Compaction scan: 1 block/batch, 1024 threads, 2 keys each.
// ---------------------------------------------------------------------------
__global__ __launch_bounds__(1024) void compact_scan_kernel(const int* __restrict__ mask)
{
    __shared__ int ssum[1024];
    const int b = blockIdx.x, t = threadIdx.x;
    const int* m = mask + (size_t)b * LK;
    const int f0 = (m[2 * t]     == 0) ? 1 : 0;
    const int f1 = (m[2 * t + 1] == 0) ? 1 : 0;
    ssum[t] = f0 + f1;
    __syncthreads();
    for (int off = 1; off < 1024; off <<= 1) {
        const int v = (t >= off) ? ssum[t - off] : 0;
        __syncthreads();
        ssum[t] += v;
        __syncthreads();
    }
    const int excl = ssum[t] - f0 - f1;
    if (f0) g_kidx[(size_t)b * LK + excl]      = 2 * t;
    if (f1) g_kidx[(size_t)b * LK + excl + f0] = 2 * t + 1;
    const int n = ssum[1023];
    if (t == 0) {
        g_nkv[b]  = n;
        g_npad[b] = (n + 127) & ~127;
    }
    g_biasc[(size_t)b * LK + 2 * t]     = (2 * t     < n) ? 0.0f : -1.0e30f;
    g_biasc[(size_t)b * LK + 2 * t + 1] = (2 * t + 1 < n) ? 0.0f : -1.0e30f;
}

// ---------------------------------------------------------------------------
// Fused gather + split: f32 kv_input rows -> compact split-bf16 (pads zeroed).
// ---------------------------------------------------------------------------
__global__ __launch_bounds__(256) void gather_split_kernel(const float* __restrict__ kv_in)
{
    const int b  = blockIdx.y;
    const int j0 = blockIdx.x * 8;
    const int n = g_nkv[b], npad = g_npad[b];
    if (j0 >= npad) return;
    const int tid = threadIdx.x;
    for (int i = tid; i < 8 * 256; i += 256) {
        const int r = i >> 8, c = i & 255;
        const int j = j0 + r;
        if (j >= npad) continue;
        uint2 uh = make_uint2(0, 0), ul = make_uint2(0, 0);
        if (j < n) {
            const int src = g_kidx[(size_t)b * LK + j];
            float4 v = reinterpret_cast<const float4*>(kv_in)
                           [((size_t)b * LK + src) * 256 + c];
            uint32_t h0, l0, h1, l1;
            split2(v.x, v.y, h0, l0);
            split2(v.z, v.w, h1, l1);
            uh = make_uint2(h0, h1);
            ul = make_uint2(l0, l1);
        }
        const size_t dof = ((size_t)b * LK + j) * 256 + c;
        reinterpret_cast<uint2*>(g_ckinh)[dof] = uh;
        reinterpret_cast<uint2*>(g_ckinl)[dof] = ul;
    }
}

// ---------------------------------------------------------------------------
// GEMM core: 128x128 tile, BK=32, 256 thr, 2-stage cp.async, fragment reuse.
// 2 CTAs/SM. Pass-major MMA ordering: 16 independent accumulators between
// dependent reuses (breaks the RAW HMMA chain).
// ---------------------------------------------------------------------------
#define G_STG 37888   // Ah 10240 + Al 10240 + Bh 8704 + Bl 8704
#define GDSM  (2 * G_STG)

__device__ __forceinline__ void gemm_core(
    const __nv_bfloat16* __restrict__ Ahg, const __nv_bfloat16* __restrict__ Alg,
    const __nv_bfloat16* __restrict__ Whg, const __nv_bfloat16* __restrict__ Wlg,
    int brow, int bcol, char* dsm, float acc[4][4][4])
{
    const uint32_t sb = smem_u32(dsm);
    const int tid  = threadIdx.x;
    const int warp = tid >> 5, lane = tid & 31;
    const int wm   = warp >> 2, wn = warp & 3;

#pragma unroll
    for (int mi = 0; mi < 4; mi++)
#pragma unroll
        for (int ni = 0; ni < 4; ni++)
#pragma unroll
            for (int r = 0; r < 4; r++) acc[mi][ni][r] = 0.0f;

    auto issue = [&](int kt, int s) {
        const int k0 = kt * 32;
        const uint32_t st = sb + s * G_STG;
#pragma unroll
        for (int i = 0; i < 2; i++) {
            const int idx = i * 256 + tid;
            const int r = idx >> 2, c = idx & 3;
            const uint32_t d = st + r * 80 + c * 16;
            const size_t go = (size_t)(brow + r) * D_MODEL + k0 + c * 8;
            cp16(d,         Ahg + go);
            cp16(d + 10240, Alg + go);
        }
#pragma unroll
        for (int i = 0; i < 2; i++) {
            const int idx = i * 256 + tid;
            const int r = idx >> 4, c = idx & 15;
            const uint32_t d = st + 20480 + r * 272 + c * 16;
            const size_t go = (size_t)(k0 + r) * D_MODEL + bcol + c * 8;
            cp16(d,        Whg + go);
            cp16(d + 8704, Wlg + go);
        }
        cp_commit();
    };

    const int NK = D_MODEL / 32;
    issue(0, 0);
    for (int kt = 0; kt < NK; kt++) {
        const int s = kt & 1;
        if (kt + 1 < NK) {
            issue(kt + 1, s ^ 1);
            asm volatile("cp.async.wait_group 1;" ::: "memory");
        } else {
            asm volatile("cp.async.wait_group 0;" ::: "memory");
        }
        __syncthreads();

        const uint32_t ah = sb + s * G_STG;
        const uint32_t al = ah + 10240;
        const uint32_t bh = ah + 20480;
        const uint32_t bl = ah + 29184;

#pragma unroll
        for (int ks = 0; ks < 2; ks++) {
            uint32_t afh[4][4], afl[4][4], bfh[2][4], bfl[2][4];
#pragma unroll
            for (int mi = 0; mi < 4; mi++) {
                const int row = wm * 64 + mi * 16 + (lane & 15);
                const int col = ks * 16 + (lane >> 4) * 8;
                const uint32_t off = (uint32_t)(row * 40 + col) * 2;
                ldm_x4(afh[mi], ah + off);
                ldm_x4(afl[mi], al + off);
            }
#pragma unroll
            for (int np = 0; np < 2; np++) {
                const int krow = ks * 16 + (lane & 15);
                const int ncol = wn * 32 + np * 16 + ((lane >> 4) & 1) * 8;
                const uint32_t off = (uint32_t)(krow * 136 + ncol) * 2;
                ldm_x4_trans(bfh[np], bh + off);
                ldm_x4_trans(bfl[np], bl + off);
            }
            // pass-major: per accumulator the term order stays hh, hl, lh
            // (numerically identical to the previous ordering).
#pragma unroll
            for (int mi = 0; mi < 4; mi++)
#pragma unroll
                for (int ni = 0; ni < 4; ni++)
                    mma_bf16(acc[mi][ni], afh[mi], &bfh[ni >> 1][(ni & 1) * 2]);
#pragma unroll
            for (int mi = 0; mi < 4; mi++)
#pragma unroll
                for (int ni = 0; ni < 4; ni++)
                    mma_bf16(acc[mi][ni], afh[mi], &bfl[ni >> 1][(ni & 1) * 2]);
#pragma unroll
            for (int mi = 0; mi < 4; mi++)
#pragma unroll
                for (int ni = 0; ni < 4; ni++)
                    mma_bf16(acc[mi][ni], afl[mi], &bfh[ni >> 1][(ni & 1) * 2]);
        }
        __syncthreads();
    }
}

// ---------------------------------------------------------------------------
// Fused Q + K + V projection GEMM. grid (16, 96).
// ---------------------------------------------------------------------------
__global__ __launch_bounds__(256, 2) void gemm_qkv(
    const float* __restrict__ bQ, const float* __restrict__ bK,
    const float* __restrict__ bV)
{
    extern __shared__ __align__(16) char dsm[];

    const __nv_bfloat16 *Ahg, *Alg, *Whg, *Wlg;
    const float* bias;
    __nv_bfloat16 *Ch, *Cl;
    float scale;
    int brow, bx = blockIdx.x;

    if (blockIdx.y < 32) {
        if (bx >= 8) return;
        Ahg = g_qinh; Alg = g_qinl; Whg = g_wqh; Wlg = g_wql;
        bias = bQ; Ch = g_qh; Cl = g_ql; scale = 0.125f;
        brow = blockIdx.y * 128;
    } else {
        brow = (blockIdx.y - 32) * 128;
        const int bb = brow / LK;
        if ((brow % LK) >= g_npad[bb]) return;
        Ahg = g_ckinh; Alg = g_ckinl; scale = 1.0f;
        if (bx < 8) { Whg = g_wkh; Wlg = g_wkl; bias = bK; Ch = g_kh; Cl = g_kl; }
        else { bx -= 8; Whg = g_wvh; Wlg = g_wvl; bias = bV; Ch = g_vh; Cl = g_vl; }
    }
    const int bcol = bx * 128;

    float acc[4][4][4];
    gemm_core(Ahg, Alg, Whg, Wlg, brow, bcol, dsm, acc);

    const int lane = threadIdx.x & 31, warp = threadIdx.x >> 5;
    const int wm = warp >> 2, wn = warp & 3;
    const int g = lane >> 2, t4 = lane & 3;
#pragma unroll
    for (int mi = 0; mi < 4; mi++) {
        const int row = brow + wm * 64 + mi * 16 + g;
#pragma unroll
        for (int ni = 0; ni < 4; ni++) {
            const int col = bcol + wn * 32 + ni * 8 + 2 * t4;
            const float b0 = bias[col], b1 = bias[col + 1];
            uint32_t h0, l0, h1, l1;
            split2((acc[mi][ni][0] + b0) * scale, (acc[mi][ni][1] + b1) * scale, h0, l0);
            split2((acc[mi][ni][2] + b0) * scale, (acc[mi][ni][3] + b1) * scale, h1, l1);
            *reinterpret_cast<uint32_t*>(&Ch[(size_t)row * D_MODEL + col])       = h0;
            *reinterpret_cast<uint32_t*>(&Cl[(size_t)row * D_MODEL + col])       = l0;
            *reinterpret_cast<uint32_t*>(&Ch[(size_t)(row + 8) * D_MODEL + col]) = h1;
            *reinterpret_cast<uint32_t*>(&Cl[(size_t)(row + 8) * D_MODEL + col]) = l1;
        }
    }
}

// Output projection: fp32 out to d_out.
__global__ __launch_bounds__(256, 2) void gemm_o(
    const float* __restrict__ bO, float* __restrict__ C)
{
    extern __shared__ __align__(16) char dsm[];
    const int brow = blockIdx.y * 128;
    const int bcol = blockIdx.x * 128;

    float acc[4][4][4];
    gemm_core(g_ah, g_al, g_woh, g_wol, brow, bcol, dsm, acc);

    const int lane = threadIdx.x & 31, warp = threadIdx.x >> 5;
    const int wm = warp >> 2, wn = warp & 3;
    const int g = lane >> 2, t4 = lane & 3;
#pragma unroll
    for (int mi = 0; mi < 4; mi++) {
        const int row = brow + wm * 64 + mi * 16 + g;
#pragma unroll
        for (int ni = 0; ni < 4; ni++) {
            const int col = bcol + wn * 32 + ni * 8 + 2 * t4;
            const float b0 = bO[col], b1 = bO[col + 1];
            *reinterpret_cast<float2*>(C + (size_t)row * D_MODEL + col) =
                make_float2(acc[mi][ni][0] + b0, acc[mi][ni][1] + b1);
            *reinterpret_cast<float2*>(C + (size_t)(row + 8) * D_MODEL + col) =
                make_float2(acc[mi][ni][2] + b0, acc[mi][ni][3] + b1);
        }
    }
}

// ---------------------------------------------------------------------------
// Tensor-core flash attention over compacted keys (npad[b]/64 tiles).
// QT=64, 128 threads / 4 warps, 2 CTAs/SM, 2-stage cp.async pipeline.
// Pass-major MMA ordering inside jp-pairs (4 independent accumulators).
// ---------------------------------------------------------------------------
#define A_TS   9216
#define A_STG  (4 * A_TS)
#define A_BOFF (2 * A_STG)
#define A_DSM  (A_BOFF + 512)

__global__ __launch_bounds__(128, 2) void attn_mma()
{
    extern __shared__ __align__(16) char dsm[];
    const uint32_t sb = smem_u32(dsm);

    const int tid  = threadIdx.x;
    const int warp = tid >> 5, lane = tid & 31;
    const int g    = lane >> 2, t4 = lane & 3;
    const int q0   = blockIdx.x * 64;
    const int h    = blockIdx.y;
    const int b    = blockIdx.z;
    const int NK   = g_npad[b] / 64;

    // ---- Q fragments via stage-0 area ----
    uint32_t qfh[4][4], qfl[4][4];
    {
        const size_t qbase = ((size_t)b * LQ + q0) * D_MODEL + h * D_H;
#pragma unroll
        for (int i = 0; i < 4; i++) {
            const int idx = i * 128 + tid;
            const int r = idx >> 3, c = idx & 7;
            const size_t go = qbase + (size_t)r * D_MODEL + c * 8;
            *reinterpret_cast<uint4*>(dsm + r * 144 + c * 16) =
                *reinterpret_cast<const uint4*>(g_qh + go);
            *reinterpret_cast<uint4*>(dsm + A_TS + r * 144 + c * 16) =
                *reinterpret_cast<const uint4*>(g_ql + go);
        }
        __syncthreads();
        const int rbase = warp * 16;
#pragma unroll
        for (int s = 0; s < 4; s++) {
            const uint32_t off =
                (uint32_t)((rbase + (lane & 15)) * 72 + (lane >> 4) * 8 + s * 16) * 2;
            ldm_x4(qfh[s], sb + off);
            ldm_x4(qfl[s], sb + A_TS + off);
        }
        __syncthreads();
    }

    auto issue = [&](int kt, int s) {
        const size_t kvbase = ((size_t)b * LK + kt * 64) * D_MODEL + h * D_H;
        const uint32_t st = sb + s * A_STG;
#pragma unroll
        for (int i = 0; i < 16; i++) {
            const int tile = i >> 2;
            const int idx = (i & 3) * 128 + tid;
            const int r = idx >> 3, c = idx & 7;
            const size_t go = kvbase + (size_t)r * D_MODEL + c * 8;
            const uint32_t d = st + tile * A_TS + r * 144 + c * 16;
            const __nv_bfloat16* src =
                tile == 0 ? g_kh : tile == 1 ? g_kl : tile == 2 ? g_vh : g_vl;
            cp16(d, src + go);
        }
        if (tid < 16)
            cp16(sb + A_BOFF + s * 256 + tid * 16,
                 g_biasc + (size_t)b * LK + kt * 64 + tid * 4);
        cp_commit();
    };

    float m0 = -1.0e30f, m1 = -1.0e30f, l0 = 0.0f, l1 = 0.0f;
    float o[8][4];
#pragma unroll
    for (int j = 0; j < 8; j++)
#pragma unroll
        for (int r = 0; r < 4; r++) o[j][r] = 0.0f;

    issue(0, 0);
    for (int kt = 0; kt < NK; kt++) {
        const int st = kt & 1;
        if (kt + 1 < NK) {
            issue(kt + 1, st ^ 1);
            asm volatile("cp.async.wait_group 1;" ::: "memory");
        } else {
            asm volatile("cp.async.wait_group 0;" ::: "memory");
        }
        __syncthreads();

        const uint32_t khb = sb + st * A_STG;
        const uint32_t klb = khb + A_TS;
        const uint32_t vhb = khb + 2 * A_TS;
        const uint32_t vlb = khb + 3 * A_TS;
        const float* bias_s = reinterpret_cast<const float*>(dsm + A_BOFF + st * 256);

        // ---- S = Q K^T (3-pass split, pass-major within jp-pairs) ----
        float s[8][4];
#pragma unroll
        for (int j = 0; j < 8; j++)
#pragma unroll
            for (int r = 0; r < 4; r++) s[j][r] = 0.0f;

#pragma unroll
        for (int ks = 0; ks < 4; ks++) {
#pragma unroll
            for (int jp2 = 0; jp2 < 2; jp2++) {
                uint32_t kh4[2][4], kl4[2][4];
#pragma unroll
                for (int q = 0; q < 2; q++) {
                    const int jp = jp2 * 2 + q;
                    const int row = jp * 16 + ((lane >> 4) & 1) * 8 + (lane & 7);
                    const int col = ks * 16 + ((lane >> 3) & 1) * 8;
                    const uint32_t off = (uint32_t)(row * 72 + col) * 2;
                    ldm_x4(kh4[q], khb + off);
                    ldm_x4(kl4[q], klb + off);
                }
#pragma unroll
                for (int q = 0; q < 2; q++) {
                    const int j0 = (jp2 * 2 + q) * 2;
                    mma_bf16(s[j0],     qfh[ks], kh4[q]);
                    mma_bf16(s[j0 + 1], qfh[ks], kh4[q] + 2);
                }
#pragma unroll
                for (int q = 0; q < 2; q++) {
                    const int j0 = (jp2 * 2 + q) * 2;
                    mma_bf16(s[j0],     qfl[ks], kh4[q]);
                    mma_bf16(s[j0 + 1], qfl[ks], kh4[q] + 2);
                }
#pragma unroll
                for (int q = 0; q < 2; q++) {
                    const int j0 = (jp2 * 2 + q) * 2;
                    mma_bf16(s[j0],     qfh[ks], kl4[q]);
                    mma_bf16(s[j0 + 1], qfh[ks], kl4[q] + 2);
                }
            }
        }

        // ---- pad bias + online softmax ----
        float mx0 = -1.0e30f, mx1 = -1.0e30f;
#pragma unroll
        for (int j = 0; j < 8; j++) {
            const float b0 = bias_s[j * 8 + 2 * t4];
            const float b1 = bias_s[j * 8 + 2 * t4 + 1];
            s[j][0] += b0; s[j][1] += b1;
            s[j][2] += b0; s[j][3] += b1;
            mx0 = fmaxf(mx0, fmaxf(s[j][0], s[j][1]));
            mx1 = fmaxf(mx1, fmaxf(s[j][2], s[j][3]));
        }
        mx0 = fmaxf(mx0, __shfl_xor_sync(0xffffffffu, mx0, 1));
        mx0 = fmaxf(mx0, __shfl_xor_sync(0xffffffffu, mx0, 2));
        mx1 = fmaxf(mx1, __shfl_xor_sync(0xffffffffu, mx1, 1));
        mx1 = fmaxf(mx1, __shfl_xor_sync(0xffffffffu, mx1, 2));

        const float m0n = fmaxf(m0, mx0), m1n = fmaxf(m1, mx1);
        const float c0 = __expf(m0 - m0n), c1 = __expf(m1 - m1n);
        m0 = m0n; m1 = m1n;

        float sum0 = 0.0f, sum1 = 0.0f;
#pragma unroll
        for (int j = 0; j < 8; j++) {
            s[j][0] = __expf(s[j][0] - m0n);
            s[j][1] = __expf(s[j][1] - m0n);
            s[j][2] = __expf(s[j][2] - m1n);
            s[j][3] = __expf(s[j][3] - m1n);
            sum0 += s[j][0] + s[j][1];
            sum1 += s[j][2] + s[j][3];
        }
        sum0 += __shfl_xor_sync(0xffffffffu, sum0, 1);
        sum0 += __shfl_xor_sync(0xffffffffu, sum0, 2);
        sum1 += __shfl_xor_sync(0xffffffffu, sum1, 1);
        sum1 += __shfl_xor_sync(0xffffffffu, sum1, 2);
        l0 = l0 * c0 + sum0;
        l1 = l1 * c1 + sum1;

#pragma unroll
        for (int j = 0; j < 8; j++) {
            o[j][0] *= c0; o[j][1] *= c0;
            o[j][2] *= c1; o[j][3] *= c1;
        }

        // ---- O += P V (3-pass split, pass-major within jp-pairs) ----
#pragma unroll
        for (int ks = 0; ks < 4; ks++) {
            uint32_t pah[4], pal[4];
            split2(s[2 * ks][0],     s[2 * ks][1],     pah[0], pal[0]);
            split2(s[2 * ks][2],     s[2 * ks][3],     pah[1], pal[1]);
            split2(s[2 * ks + 1][0], s[2 * ks + 1][1], pah[2], pal[2]);
            split2(s[2 * ks + 1][2], s[2 * ks + 1][3], pah[3], pal[3]);
#pragma unroll
            for (int jp2 = 0; jp2 < 2; jp2++) {
                uint32_t vh4[2][4], vl4[2][4];
#pragma unroll
                for (int q = 0; q < 2; q++) {
                    const int jp = jp2 * 2 + q;
                    const int row = ks * 16 + (lane & 15);
                    const int col = jp * 16 + ((lane >> 4) & 1) * 8;
                    const uint32_t off = (uint32_t)(row * 72 + col) * 2;
                    ldm_x4_trans(vh4[q], vhb + off);
                    ldm_x4_trans(vl4[q], vlb + off);
                }
#pragma unroll
                for (int q = 0; q < 2; q++) {
                    const int j0 = (jp2 * 2 + q) * 2;
                    mma_bf16(o[j0],     pah, vh4[q]);
                    mma_bf16(o[j0 + 1], pah, vh4[q] + 2);
                }
#pragma unroll
                for (int q = 0; q < 2; q++) {
                    const int j0 = (jp2 * 2 + q) * 2;
                    mma_bf16(o[j0],     pal, vh4[q]);
                    mma_bf16(o[j0 + 1], pal, vh4[q] + 2);
                }
#pragma unroll
                for (int q = 0; q < 2; q++) {
                    const int j0 = (jp2 * 2 + q) * 2;
                    mma_bf16(o[j0],     pah, vl4[q]);
                    mma_bf16(o[j0 + 1], pah, vl4[q] + 2);
                }
            }
        }
        __syncthreads();
    }

    // ---- normalize + write split-bf16 output ----
    const float li0 = 1.0f / l0, li1 = 1.0f / l1;
    const int row0 = q0 + warp * 16 + g;
    const size_t base0 = ((size_t)b * LQ + row0) * D_MODEL + h * D_H;
    const size_t base1 = base0 + (size_t)8 * D_MODEL;
#pragma unroll
    for (int j = 0; j < 8; j++) {
        const int col = j * 8 + 2 * t4;
        uint32_t h0, l0r, h1, l1r;
        split2(o[j][0] * li0, o[j][1] * li0, h0, l0r);
        split2(o[j][2] * li1, o[j][3] * li1, h1, l1r);
        *reinterpret_cast<uint32_t*>(&g_ah[base0 + col]) = h0;
        *reinterpret_cast<uint32_t*>(&g_al[base0 + col]) = l0r;
        *reinterpret_cast<uint32_t*>(&g_ah[base1 + col]) = h1;
        *reinterpret_cast<uint32_t*>(&g_al[base1 + col]) = l1r;
    }
}

// ---------------------------------------------------------------------------
// Launch
// ---------------------------------------------------------------------------
extern "C" void kernel_launch(void* const* d_in, const int* in_sizes, int n_in,
                              void* d_out, int out_size)
{
    const float* q_in  = (const float*)d_in[0];
    const float* kv_in = (const float*)d_in[1];
    const int*   mask  = (const int*)  d_in[2];
    const float* W_Q   = (const float*)d_in[3];
    const float* b_Q   = (const float*)d_in[4];
    const float* W_K   = (const float*)d_in[5];
    const float* b_K   = (const float*)d_in[6];
    const float* W_V   = (const float*)d_in[7];
    const float* b_V   = (const float*)d_in[8];
    const float* W_O   = (const float*)d_in[9];
    const float* b_O   = (const float*)d_in[10];

    cudaFuncSetAttribute(gemm_qkv, cudaFuncAttributeMaxDynamicSharedMemorySize, GDSM);
    cudaFuncSetAttribute(gemm_o,   cudaFuncAttributeMaxDynamicSharedMemorySize, GDSM);
    cudaFuncSetAttribute(attn_mma, cudaFuncAttributeMaxDynamicSharedMemorySize, A_DSM);

    // ---- preprocessing: splits + compaction ----
    split_all_kernel<<<8192, 256>>>(q_in, W_Q, W_K, W_V, W_O);
    compact_scan_kernel<<<BATCH, 1024>>>(mask);
    gather_split_kernel<<<dim3(LK / 8, BATCH), 256>>>(kv_in);

    // ---- fused Q/K/V projections ----
    gemm_qkv<<<dim3(16, 96), 256, GDSM>>>(b_Q, b_K, b_V);

    // ---- attention over compacted keys ----
    attn_mma<<<dim3(LQ / 64, N_HEAD, BATCH), 128, A_DSM>>>();

    // ---- output projection ----
    gemm_o<<<dim3(8, 32), 256, GDSM>>>(b_O, (float*)d_out);
}

// round 12
// speedup vs baseline: 1.2862x; 1.2560x over previous
#include <cuda_runtime.h>
#include <cuda_fp16.h>
#include <stdint.h>
#include <math.h>

#define D_MODEL 1024
#define N_HEAD  16
#define D_H     64
#define BATCH   4
#define LQ      1024
#define LK      2048

// ---------------------------------------------------------------------------
// Scratch (no cudaMalloc allowed)
// ---------------------------------------------------------------------------
__device__ __half g_qinh [(size_t)BATCH * LQ * D_MODEL];   // fp16 activation (hi only)
__device__ __half g_ckinh[(size_t)BATCH * LK * D_MODEL];   // compacted kv input (hi only)
__device__ __half g_wqh[(size_t)D_MODEL * D_MODEL];
__device__ __half g_wql[(size_t)D_MODEL * D_MODEL];
__device__ __half g_wkh[(size_t)D_MODEL * D_MODEL];
__device__ __half g_wkl[(size_t)D_MODEL * D_MODEL];
__device__ __half g_wvh[(size_t)D_MODEL * D_MODEL];
__device__ __half g_wvl[(size_t)D_MODEL * D_MODEL];
__device__ __half g_woh[(size_t)D_MODEL * D_MODEL];
__device__ __half g_wol[(size_t)D_MODEL * D_MODEL];
// projections: fp16 hi/lo (3-pass attention needs both)
__device__ __half g_qh[(size_t)BATCH * LQ * D_MODEL];
__device__ __half g_ql[(size_t)BATCH * LQ * D_MODEL];
__device__ __half g_kh[(size_t)BATCH * LK * D_MODEL];
__device__ __half g_kl[(size_t)BATCH * LK * D_MODEL];
__device__ __half g_vh[(size_t)BATCH * LK * D_MODEL];
__device__ __half g_vl[(size_t)BATCH * LK * D_MODEL];
// attention output: single fp16 (gemm_o rounds the activation anyway)
__device__ __half g_ah[(size_t)BATCH * LQ * D_MODEL];
// compaction metadata
__device__ int   g_kidx[(size_t)BATCH * LK];
__device__ int   g_nkv[BATCH];
__device__ int   g_npad[BATCH];
__device__ float g_biasc[(size_t)BATCH * LK];

// ---------------------------------------------------------------------------
// Helpers
// ---------------------------------------------------------------------------
__device__ __forceinline__ uint32_t smem_u32(const void* p) {
    uint32_t a;
    asm("{ .reg .u64 t; cvta.to.shared.u64 t, %1; cvt.u32.u64 %0, t; }"
        : "=r"(a) : "l"(p));
    return a;
}
__device__ __forceinline__ void cp16(uint32_t d, const void* g) {
    asm volatile("cp.async.cg.shared.global [%0], [%1], 16;" :: "r"(d), "l"(g));
}
__device__ __forceinline__ void cp_commit() {
    asm volatile("cp.async.commit_group;" ::: "memory");
}
__device__ __forceinline__ void ldm_x4(uint32_t* r, uint32_t addr) {
    asm volatile("ldmatrix.sync.aligned.m8n8.x4.shared.b16 {%0,%1,%2,%3}, [%4];"
                 : "=r"(r[0]), "=r"(r[1]), "=r"(r[2]), "=r"(r[3]) : "r"(addr));
}
__device__ __forceinline__ void ldm_x4_trans(uint32_t* r, uint32_t addr) {
    asm volatile("ldmatrix.sync.aligned.m8n8.x4.trans.shared.b16 {%0,%1,%2,%3}, [%4];"
                 : "=r"(r[0]), "=r"(r[1]), "=r"(r[2]), "=r"(r[3]) : "r"(addr));
}
__device__ __forceinline__ void mma_f16(float* c, const uint32_t* a, const uint32_t* b) {
    asm volatile(
        "mma.sync.aligned.m16n8k16.row.col.f32.f16.f16.f32 "
        "{%0,%1,%2,%3}, {%4,%5,%6,%7}, {%8,%9}, {%0,%1,%2,%3};"
        : "+f"(c[0]), "+f"(c[1]), "+f"(c[2]), "+f"(c[3])
        : "r"(a[0]), "r"(a[1]), "r"(a[2]), "r"(a[3]), "r"(b[0]), "r"(b[1]));
}
// fp16 split: pair -> hi half2 + lo half2 (packed u32)
__device__ __forceinline__ void split2h(float a, float b, uint32_t& hi, uint32_t& lo) {
    __half2 h2 = __floats2half2_rn(a, b);
    float2 hf = __half22float2(h2);
    __half2 l2 = __floats2half2_rn(a - hf.x, b - hf.y);
    hi = *reinterpret_cast<uint32_t*>(&h2);
    lo = *reinterpret_cast<uint32_t*>(&l2);
}
__device__ __forceinline__ uint32_t pack2h(float a, float b) {
    __half2 h2 = __floats2half2_rn(a, b);
    return *reinterpret_cast<uint32_t*>(&h2);
}

// ---------------------------------------------------------------------------
// Fused pre-split: q_input (hi only) + 4 weights (hi+lo) in one launch.
// blocks [0,4096): q_in; [4096,8192): weights (1024 blocks each).
// ---------------------------------------------------------------------------
__global__ __launch_bounds__(256) void split_all_kernel(
    const float* __restrict__ q_in,
    const float* __restrict__ WQ, const float* __restrict__ WK,
    const float* __restrict__ WV, const float* __restrict__ WO)
{
    const int blk = blockIdx.x;
    if (blk < 4096) {
        const int i = blk * 256 + threadIdx.x;
        float4 v = reinterpret_cast<const float4*>(q_in)[i];
        reinterpret_cast<uint2*>(g_qinh)[i] =
            make_uint2(pack2h(v.x, v.y), pack2h(v.z, v.w));
        return;
    }
    const int w = (blk - 4096) >> 10;
    const int i = ((blk - 4096) & 1023) * 256 + threadIdx.x;
    const float* src;
    __half *dh, *dl;
    switch (w) {
        case 0:  src = WQ; dh = g_wqh; dl = g_wql; break;
        case 1:  src = WK; dh = g_wkh; dl = g_wkl; break;
        case 2:  src = WV; dh = g_wvh; dl = g_wvl; break;
        default: src = WO; dh = g_woh; dl = g_wol; break;
    }
    float4 v = reinterpret_cast<const float4*>(src)[i];
    uint32_t h0, l0, h1, l1;
    split2h(v.x, v.y, h0, l0);
    split2h(v.z, v.w, h1, l1);
    reinterpret_cast<uint2*>(dh)[i] = make_uint2(h0, h1);
    reinterpret_cast<uint2*>(dl)[i] = make_uint2(l0, l1);
}

// ---------------------------------------------------------------------------
// Compaction scan: 1 block/batch, 1024 threads, 2 keys each.
// ---------------------------------------------------------------------------
__global__ __launch_bounds__(1024) void compact_scan_kernel(const int* __restrict__ mask)
{
    __shared__ int ssum[1024];
    const int b = blockIdx.x, t = threadIdx.x;
    const int* m = mask + (size_t)b * LK;
    const int f0 = (m[2 * t]     == 0) ? 1 : 0;
    const int f1 = (m[2 * t + 1] == 0) ? 1 : 0;
    ssum[t] = f0 + f1;
    __syncthreads();
    for (int off = 1; off < 1024; off <<= 1) {
        const int v = (t >= off) ? ssum[t - off] : 0;
        __syncthreads();
        ssum[t] += v;
        __syncthreads();
    }
    const int excl = ssum[t] - f0 - f1;
    if (f0) g_kidx[(size_t)b * LK + excl]      = 2 * t;
    if (f1) g_kidx[(size_t)b * LK + excl + f0] = 2 * t + 1;
    const int n = ssum[1023];
    if (t == 0) {
        g_nkv[b]  = n;
        g_npad[b] = (n + 127) & ~127;
    }
    g_biasc[(size_t)b * LK + 2 * t]     = (2 * t     < n) ? 0.0f : -1.0e30f;
    g_biasc[(size_t)b * LK + 2 * t + 1] = (2 * t + 1 < n) ? 0.0f : -1.0e30f;
}

// ---------------------------------------------------------------------------
// Fused gather + round: f32 kv rows -> compact fp16 (hi only; pads zeroed).
// ---------------------------------------------------------------------------
__global__ __launch_bounds__(256) void gather_split_kernel(const float* __restrict__ kv_in)
{
    const int b  = blockIdx.y;
    const int j0 = blockIdx.x * 8;
    const int n = g_nkv[b], npad = g_npad[b];
    if (j0 >= npad) return;
    const int tid = threadIdx.x;
    for (int i = tid; i < 8 * 256; i += 256) {
        const int r = i >> 8, c = i & 255;
        const int j = j0 + r;
        if (j >= npad) continue;
        uint2 uh = make_uint2(0, 0);
        if (j < n) {
            const int src = g_kidx[(size_t)b * LK + j];
            float4 v = reinterpret_cast<const float4*>(kv_in)
                           [((size_t)b * LK + src) * 256 + c];
            uh = make_uint2(pack2h(v.x, v.y), pack2h(v.z, v.w));
        }
        reinterpret_cast<uint2*>(g_ckinh)[((size_t)b * LK + j) * 256 + c] = uh;
    }
}

// ---------------------------------------------------------------------------
// GEMM core: 128x128 tile, BK=32, 256 thr, 2-stage cp.async, 2 CTAs/SM.
// 2-pass fp16: C = Ah*Bh + Ah*Bl  (A rounded to fp16, weight split hi/lo).
// ---------------------------------------------------------------------------
#define G_STG 27648   // Ah 10240 + Bh 8704 + Bl 8704
#define GDSM  (2 * G_STG)

__device__ __forceinline__ void gemm_core(
    const __half* __restrict__ Ahg,
    const __half* __restrict__ Whg, const __half* __restrict__ Wlg,
    int brow, int bcol, char* dsm, float acc[4][4][4])
{
    const uint32_t sb = smem_u32(dsm);
    const int tid  = threadIdx.x;
    const int warp = tid >> 5, lane = tid & 31;
    const int wm   = warp >> 2, wn = warp & 3;

#pragma unroll
    for (int mi = 0; mi < 4; mi++)
#pragma unroll
        for (int ni = 0; ni < 4; ni++)
#pragma unroll
            for (int r = 0; r < 4; r++) acc[mi][ni][r] = 0.0f;

    auto issue = [&](int kt, int s) {
        const int k0 = kt * 32;
        const uint32_t st = sb + s * G_STG;
#pragma unroll
        for (int i = 0; i < 2; i++) {
            const int idx = i * 256 + tid;
            const int r = idx >> 2, c = idx & 3;
            cp16(st + r * 80 + c * 16,
                 Ahg + (size_t)(brow + r) * D_MODEL + k0 + c * 8);
        }
#pragma unroll
        for (int i = 0; i < 2; i++) {
            const int idx = i * 256 + tid;
            const int r = idx >> 4, c = idx & 15;
            const uint32_t d = st + 10240 + r * 272 + c * 16;
            const size_t go = (size_t)(k0 + r) * D_MODEL + bcol + c * 8;
            cp16(d,        Whg + go);
            cp16(d + 8704, Wlg + go);
        }
        cp_commit();
    };

    const int NK = D_MODEL / 32;
    issue(0, 0);
    for (int kt = 0; kt < NK; kt++) {
        const int s = kt & 1;
        if (kt + 1 < NK) {
            issue(kt + 1, s ^ 1);
            asm volatile("cp.async.wait_group 1;" ::: "memory");
        } else {
            asm volatile("cp.async.wait_group 0;" ::: "memory");
        }
        __syncthreads();

        const uint32_t ah = sb + s * G_STG;
        const uint32_t bh = ah + 10240;
        const uint32_t bl = ah + 18944;

#pragma unroll
        for (int ks = 0; ks < 2; ks++) {
            uint32_t afh[4][4], bfh[2][4], bfl[2][4];
#pragma unroll
            for (int mi = 0; mi < 4; mi++) {
                const int row = wm * 64 + mi * 16 + (lane & 15);
                const int col = ks * 16 + (lane >> 4) * 8;
                ldm_x4(afh[mi], ah + (uint32_t)(row * 40 + col) * 2);
            }
#pragma unroll
            for (int np = 0; np < 2; np++) {
                const int krow = ks * 16 + (lane & 15);
                const int ncol = wn * 32 + np * 16 + ((lane >> 4) & 1) * 8;
                const uint32_t off = (uint32_t)(krow * 136 + ncol) * 2;
                ldm_x4_trans(bfh[np], bh + off);
                ldm_x4_trans(bfl[np], bl + off);
            }
#pragma unroll
            for (int mi = 0; mi < 4; mi++)
#pragma unroll
                for (int ni = 0; ni < 4; ni++)
                    mma_f16(acc[mi][ni], afh[mi], &bfh[ni >> 1][(ni & 1) * 2]);
#pragma unroll
            for (int mi = 0; mi < 4; mi++)
#pragma unroll
                for (int ni = 0; ni < 4; ni++)
                    mma_f16(acc[mi][ni], afh[mi], &bfl[ni >> 1][(ni & 1) * 2]);
        }
        __syncthreads();
    }
}

// ---------------------------------------------------------------------------
// Fused Q + K + V projection GEMM. grid (16, 96). Outputs fp16 hi/lo.
// ---------------------------------------------------------------------------
__global__ __launch_bounds__(256, 2) void gemm_qkv(
    const float* __restrict__ bQ, const float* __restrict__ bK,
    const float* __restrict__ bV)
{
    extern __shared__ __align__(16) char dsm[];

    const __half *Ahg, *Whg, *Wlg;
    const float* bias;
    __half *Ch, *Cl;
    float scale;
    int brow, bx = blockIdx.x;

    if (blockIdx.y < 32) {
        if (bx >= 8) return;
        Ahg = g_qinh; Whg = g_wqh; Wlg = g_wql;
        bias = bQ; Ch = g_qh; Cl = g_ql; scale = 0.125f;
        brow = blockIdx.y * 128;
    } else {
        brow = (blockIdx.y - 32) * 128;
        const int bb = brow / LK;
        if ((brow % LK) >= g_npad[bb]) return;
        Ahg = g_ckinh; scale = 1.0f;
        if (bx < 8) { Whg = g_wkh; Wlg = g_wkl; bias = bK; Ch = g_kh; Cl = g_kl; }
        else { bx -= 8; Whg = g_wvh; Wlg = g_wvl; bias = bV; Ch = g_vh; Cl = g_vl; }
    }
    const int bcol = bx * 128;

    float acc[4][4][4];
    gemm_core(Ahg, Whg, Wlg, brow, bcol, dsm, acc);

    const int lane = threadIdx.x & 31, warp = threadIdx.x >> 5;
    const int wm = warp >> 2, wn = warp & 3;
    const int g = lane >> 2, t4 = lane & 3;
#pragma unroll
    for (int mi = 0; mi < 4; mi++) {
        const int row = brow + wm * 64 + mi * 16 + g;
#pragma unroll
        for (int ni = 0; ni < 4; ni++) {
            const int col = bcol + wn * 32 + ni * 8 + 2 * t4;
            const float b0 = bias[col], b1 = bias[col + 1];
            uint32_t h0, l0, h1, l1;
            split2h((acc[mi][ni][0] + b0) * scale, (acc[mi][ni][1] + b1) * scale, h0, l0);
            split2h((acc[mi][ni][2] + b0) * scale, (acc[mi][ni][3] + b1) * scale, h1, l1);
            *reinterpret_cast<uint32_t*>(&Ch[(size_t)row * D_MODEL + col])       = h0;
            *reinterpret_cast<uint32_t*>(&Cl[(size_t)row * D_MODEL + col])       = l0;
            *reinterpret_cast<uint32_t*>(&Ch[(size_t)(row + 8) * D_MODEL + col]) = h1;
            *reinterpret_cast<uint32_t*>(&Cl[(size_t)(row + 8) * D_MODEL + col]) = l1;
        }
    }
}

// Output projection: fp32 out to d_out.
__global__ __launch_bounds__(256, 2) void gemm_o(
    const float* __restrict__ bO, float* __restrict__ C)
{
    extern __shared__ __align__(16) char dsm[];
    const int brow = blockIdx.y * 128;
    const int bcol = blockIdx.x * 128;

    float acc[4][4][4];
    gemm_core(g_ah, g_woh, g_wol, brow, bcol, dsm, acc);

    const int lane = threadIdx.x & 31, warp = threadIdx.x >> 5;
    const int wm = warp >> 2, wn = warp & 3;
    const int g = lane >> 2, t4 = lane & 3;
#pragma unroll
    for (int mi = 0; mi < 4; mi++) {
        const int row = brow + wm * 64 + mi * 16 + g;
#pragma unroll
        for (int ni = 0; ni < 4; ni++) {
            const int col = bcol + wn * 32 + ni * 8 + 2 * t4;
            const float b0 = bO[col], b1 = bO[col + 1];
            *reinterpret_cast<float2*>(C + (size_t)row * D_MODEL + col) =
                make_float2(acc[mi][ni][0] + b0, acc[mi][ni][1] + b1);
            *reinterpret_cast<float2*>(C + (size_t)(row + 8) * D_MODEL + col) =
                make_float2(acc[mi][ni][2] + b0, acc[mi][ni][3] + b1);
        }
    }
}

// ---------------------------------------------------------------------------
// fp16 tensor-core flash attention over compacted keys (3-pass split; the
// fp16 splits make the attention error negligible).
// QT=64, 128 threads / 4 warps, 2 CTAs/SM, 2-stage cp.async pipeline.
// ---------------------------------------------------------------------------
#define A_TS   9216
#define A_STG  (4 * A_TS)
#define A_BOFF (2 * A_STG)
#define A_DSM  (A_BOFF + 512)

__global__ __launch_bounds__(128, 2) void attn_mma()
{
    extern __shared__ __align__(16) char dsm[];
    const uint32_t sb = smem_u32(dsm);

    const int tid  = threadIdx.x;
    const int warp = tid >> 5, lane = tid & 31;
    const int g    = lane >> 2, t4 = lane & 3;
    const int q0   = blockIdx.x * 64;
    const int h    = blockIdx.y;
    const int b    = blockIdx.z;
    const int NK   = g_npad[b] / 64;

    // ---- Q fragments via stage-0 area ----
    uint32_t qfh[4][4], qfl[4][4];
    {
        const size_t qbase = ((size_t)b * LQ + q0) * D_MODEL + h * D_H;
#pragma unroll
        for (int i = 0; i < 4; i++) {
            const int idx = i * 128 + tid;
            const int r = idx >> 3, c = idx & 7;
            const size_t go = qbase + (size_t)r * D_MODEL + c * 8;
            *reinterpret_cast<uint4*>(dsm + r * 144 + c * 16) =
                *reinterpret_cast<const uint4*>(g_qh + go);
            *reinterpret_cast<uint4*>(dsm + A_TS + r * 144 + c * 16) =
                *reinterpret_cast<const uint4*>(g_ql + go);
        }
        __syncthreads();
        const int rbase = warp * 16;
#pragma unroll
        for (int s = 0; s < 4; s++) {
            const uint32_t off =
                (uint32_t)((rbase + (lane & 15)) * 72 + (lane >> 4) * 8 + s * 16) * 2;
            ldm_x4(qfh[s], sb + off);
            ldm_x4(qfl[s], sb + A_TS + off);
        }
        __syncthreads();
    }

    auto issue = [&](int kt, int s) {
        const size_t kvbase = ((size_t)b * LK + kt * 64) * D_MODEL + h * D_H;
        const uint32_t st = sb + s * A_STG;
#pragma unroll
        for (int i = 0; i < 16; i++) {
            const int tile = i >> 2;
            const int idx = (i & 3) * 128 + tid;
            const int r = idx >> 3, c = idx & 7;
            const size_t go = kvbase + (size_t)r * D_MODEL + c * 8;
            const uint32_t d = st + tile * A_TS + r * 144 + c * 16;
            const __half* src =
                tile == 0 ? g_kh : tile == 1 ? g_kl : tile == 2 ? g_vh : g_vl;
            cp16(d, src + go);
        }
        if (tid < 16)
            cp16(sb + A_BOFF + s * 256 + tid * 16,
                 g_biasc + (size_t)b * LK + kt * 64 + tid * 4);
        cp_commit();
    };

    float m0 = -1.0e30f, m1 = -1.0e30f, l0 = 0.0f, l1 = 0.0f;
    float o[8][4];
#pragma unroll
    for (int j = 0; j < 8; j++)
#pragma unroll
        for (int r = 0; r < 4; r++) o[j][r] = 0.0f;

    issue(0, 0);
    for (int kt = 0; kt < NK; kt++) {
        const int st = kt & 1;
        if (kt + 1 < NK) {
            issue(kt + 1, st ^ 1);
            asm volatile("cp.async.wait_group 1;" ::: "memory");
        } else {
            asm volatile("cp.async.wait_group 0;" ::: "memory");
        }
        __syncthreads();

        const uint32_t khb = sb + st * A_STG;
        const uint32_t klb = khb + A_TS;
        const uint32_t vhb = khb + 2 * A_TS;
        const uint32_t vlb = khb + 3 * A_TS;
        const float* bias_s = reinterpret_cast<const float*>(dsm + A_BOFF + st * 256);

        // ---- S = Q K^T (3-pass fp16 split) ----
        float s[8][4];
#pragma unroll
        for (int j = 0; j < 8; j++)
#pragma unroll
            for (int r = 0; r < 4; r++) s[j][r] = 0.0f;

#pragma unroll
        for (int ks = 0; ks < 4; ks++) {
#pragma unroll
            for (int jp2 = 0; jp2 < 2; jp2++) {
                uint32_t kh4[2][4], kl4[2][4];
#pragma unroll
                for (int q = 0; q < 2; q++) {
                    const int jp = jp2 * 2 + q;
                    const int row = jp * 16 + ((lane >> 4) & 1) * 8 + (lane & 7);
                    const int col = ks * 16 + ((lane >> 3) & 1) * 8;
                    const uint32_t off = (uint32_t)(row * 72 + col) * 2;
                    ldm_x4(kh4[q], khb + off);
                    ldm_x4(kl4[q], klb + off);
                }
#pragma unroll
                for (int q = 0; q < 2; q++) {
                    const int j0 = (jp2 * 2 + q) * 2;
                    mma_f16(s[j0],     qfh[ks], kh4[q]);
                    mma_f16(s[j0 + 1], qfh[ks], kh4[q] + 2);
                }
#pragma unroll
                for (int q = 0; q < 2; q++) {
                    const int j0 = (jp2 * 2 + q) * 2;
                    mma_f16(s[j0],     qfl[ks], kh4[q]);
                    mma_f16(s[j0 + 1], qfl[ks], kh4[q] + 2);
                }
#pragma unroll
                for (int q = 0; q < 2; q++) {
                    const int j0 = (jp2 * 2 + q) * 2;
                    mma_f16(s[j0],     qfh[ks], kl4[q]);
                    mma_f16(s[j0 + 1], qfh[ks], kl4[q] + 2);
                }
            }
        }

        // ---- pad bias + online softmax ----
        float mx0 = -1.0e30f, mx1 = -1.0e30f;
#pragma unroll
        for (int j = 0; j < 8; j++) {
            const float b0 = bias_s[j * 8 + 2 * t4];
            const float b1 = bias_s[j * 8 + 2 * t4 + 1];
            s[j][0] += b0; s[j][1] += b1;
            s[j][2] += b0; s[j][3] += b1;
            mx0 = fmaxf(mx0, fmaxf(s[j][0], s[j][1]));
            mx1 = fmaxf(mx1, fmaxf(s[j][2], s[j][3]));
        }
        mx0 = fmaxf(mx0, __shfl_xor_sync(0xffffffffu, mx0, 1));
        mx0 = fmaxf(mx0, __shfl_xor_sync(0xffffffffu, mx0, 2));
        mx1 = fmaxf(mx1, __shfl_xor_sync(0xffffffffu, mx1, 1));
        mx1 = fmaxf(mx1, __shfl_xor_sync(0xffffffffu, mx1, 2));

        const float m0n = fmaxf(m0, mx0), m1n = fmaxf(m1, mx1);
        const float c0 = __expf(m0 - m0n), c1 = __expf(m1 - m1n);
        m0 = m0n; m1 = m1n;

        float sum0 = 0.0f, sum1 = 0.0f;
#pragma unroll
        for (int j = 0; j < 8; j++) {
            s[j][0] = __expf(s[j][0] - m0n);
            s[j][1] = __expf(s[j][1] - m0n);
            s[j][2] = __expf(s[j][2] - m1n);
            s[j][3] = __expf(s[j][3] - m1n);
            sum0 += s[j][0] + s[j][1];
            sum1 += s[j][2] + s[j][3];
        }
        sum0 += __shfl_xor_sync(0xffffffffu, sum0, 1);
        sum0 += __shfl_xor_sync(0xffffffffu, sum0, 2);
        sum1 += __shfl_xor_sync(0xffffffffu, sum1, 1);
        sum1 += __shfl_xor_sync(0xffffffffu, sum1, 2);
        l0 = l0 * c0 + sum0;
        l1 = l1 * c1 + sum1;

#pragma unroll
        for (int j = 0; j < 8; j++) {
            o[j][0] *= c0; o[j][1] *= c0;
            o[j][2] *= c1; o[j][3] *= c1;
        }

        // ---- O += P V (3-pass fp16 split) ----
#pragma unroll
        for (int ks = 0; ks < 4; ks++) {
            uint32_t pah[4], pal[4];
            split2h(s[2 * ks][0],     s[2 * ks][1],     pah[0], pal[0]);
            split2h(s[2 * ks][2],     s[2 * ks][3],     pah[1], pal[1]);
            split2h(s[2 * ks + 1][0], s[2 * ks + 1][1], pah[2], pal[2]);
            split2h(s[2 * ks + 1][2], s[2 * ks + 1][3], pah[3], pal[3]);
#pragma unroll
            for (int jp2 = 0; jp2 < 2; jp2++) {
                uint32_t vh4[2][4], vl4[2][4];
#pragma unroll
                for (int q = 0; q < 2; q++) {
                    const int jp = jp2 * 2 + q;
                    const int row = ks * 16 + (lane & 15);
                    const int col = jp * 16 + ((lane >> 4) & 1) * 8;
                    const uint32_t off = (uint32_t)(row * 72 + col) * 2;
                    ldm_x4_trans(vh4[q], vhb + off);
                    ldm_x4_trans(vl4[q], vlb + off);
                }
#pragma unroll
                for (int q = 0; q < 2; q++) {
                    const int j0 = (jp2 * 2 + q) * 2;
                    mma_f16(o[j0],     pah, vh4[q]);
                    mma_f16(o[j0 + 1], pah, vh4[q] + 2);
                }
#pragma unroll
                for (int q = 0; q < 2; q++) {
                    const int j0 = (jp2 * 2 + q) * 2;
                    mma_f16(o[j0],     pal, vh4[q]);
                    mma_f16(o[j0 + 1], pal, vh4[q] + 2);
                }
#pragma unroll
                for (int q = 0; q < 2; q++) {
                    const int j0 = (jp2 * 2 + q) * 2;
                    mma_f16(o[j0],     pah, vl4[q]);
                    mma_f16(o[j0 + 1], pah, vl4[q] + 2);
                }
            }
        }
        __syncthreads();
    }

    // ---- normalize + write single-fp16 output ----
    const float li0 = 1.0f / l0, li1 = 1.0f / l1;
    const int row0 = q0 + warp * 16 + g;
    const size_t base0 = ((size_t)b * LQ + row0) * D_MODEL + h * D_H;
    const size_t base1 = base0 + (size_t)8 * D_MODEL;
#pragma unroll
    for (int j = 0; j < 8; j++) {
        const int col = j * 8 + 2 * t4;
        *reinterpret_cast<uint32_t*>(&g_ah[base0 + col]) =
            pack2h(o[j][0] * li0, o[j][1] * li0);
        *reinterpret_cast<uint32_t*>(&g_ah[base1 + col]) =
            pack2h(o[j][2] * li1, o[j][3] * li1);
    }
}

// ---------------------------------------------------------------------------
// Launch
// ---------------------------------------------------------------------------
extern "C" void kernel_launch(void* const* d_in, const int* in_sizes, int n_in,
                              void* d_out, int out_size)
{
    const float* q_in  = (const float*)d_in[0];
    const float* kv_in = (const float*)d_in[1];
    const int*   mask  = (const int*)  d_in[2];
    const float* W_Q   = (const float*)d_in[3];
    const float* b_Q   = (const float*)d_in[4];
    const float* W_K   = (const float*)d_in[5];
    const float* b_K   = (const float*)d_in[6];
    const float* W_V   = (const float*)d_in[7];
    const float* b_V   = (const float*)d_in[8];
    const float* W_O   = (const float*)d_in[9];
    const float* b_O   = (const float*)d_in[10];

    cudaFuncSetAttribute(gemm_qkv, cudaFuncAttributeMaxDynamicSharedMemorySize, GDSM);
    cudaFuncSetAttribute(gemm_o,   cudaFuncAttributeMaxDynamicSharedMemorySize, GDSM);
    cudaFuncSetAttribute(attn_mma, cudaFuncAttributeMaxDynamicSharedMemorySize, A_DSM);

    // ---- preprocessing: splits + compaction ----
    split_all_kernel<<<8192, 256>>>(q_in, W_Q, W_K, W_V, W_O);
    compact_scan_kernel<<<BATCH, 1024>>>(mask);
    gather_split_kernel<<<dim3(LK / 8, BATCH), 256>>>(kv_in);

    // ---- fused Q/K/V projections ----
    gemm_qkv<<<dim3(16, 96), 256, GDSM>>>(b_Q, b_K, b_V);

    // ---- attention over compacted keys ----
    attn_mma<<<dim3(LQ / 64, N_HEAD, BATCH), 128, A_DSM>>>();

    // ---- output projection ----
    gemm_o<<<dim3(8, 32), 256, GDSM>>>(b_O, (float*)d_out);
}

// round 13
// speedup vs baseline: 1.4391x; 1.1189x over previous
#include <cuda_runtime.h>
#include <cuda_fp16.h>
#include <stdint.h>
#include <math.h>

#define D_MODEL 1024
#define N_HEAD  16
#define D_H     64
#define BATCH   4
#define LQ      1024
#define LK      2048

// ---------------------------------------------------------------------------
// Scratch (no cudaMalloc allowed)
// ---------------------------------------------------------------------------
__device__ __half g_qinh [(size_t)BATCH * LQ * D_MODEL];   // fp16 activation (hi only)
__device__ __half g_ckinh[(size_t)BATCH * LK * D_MODEL];   // compacted kv input (hi only)
__device__ __half g_wqh[(size_t)D_MODEL * D_MODEL];
__device__ __half g_wql[(size_t)D_MODEL * D_MODEL];
__device__ __half g_wkh[(size_t)D_MODEL * D_MODEL];
__device__ __half g_wkl[(size_t)D_MODEL * D_MODEL];
__device__ __half g_wvh[(size_t)D_MODEL * D_MODEL];
__device__ __half g_wvl[(size_t)D_MODEL * D_MODEL];
__device__ __half g_woh[(size_t)D_MODEL * D_MODEL];
__device__ __half g_wol[(size_t)D_MODEL * D_MODEL];
// projections: Q rounded (hi only); K/V split hi/lo (weight side of attention)
__device__ __half g_qh[(size_t)BATCH * LQ * D_MODEL];
__device__ __half g_kh[(size_t)BATCH * LK * D_MODEL];
__device__ __half g_kl[(size_t)BATCH * LK * D_MODEL];
__device__ __half g_vh[(size_t)BATCH * LK * D_MODEL];
__device__ __half g_vl[(size_t)BATCH * LK * D_MODEL];
// attention output: single fp16
__device__ __half g_ah[(size_t)BATCH * LQ * D_MODEL];
// compaction metadata
__device__ int   g_kidx[(size_t)BATCH * LK];
__device__ int   g_nkv[BATCH];
__device__ int   g_npad[BATCH];
__device__ float g_biasc[(size_t)BATCH * LK];

// ---------------------------------------------------------------------------
// Helpers
// ---------------------------------------------------------------------------
__device__ __forceinline__ uint32_t smem_u32(const void* p) {
    uint32_t a;
    asm("{ .reg .u64 t; cvta.to.shared.u64 t, %1; cvt.u32.u64 %0, t; }"
        : "=r"(a) : "l"(p));
    return a;
}
__device__ __forceinline__ void cp16(uint32_t d, const void* g) {
    asm volatile("cp.async.cg.shared.global [%0], [%1], 16;" :: "r"(d), "l"(g));
}
__device__ __forceinline__ void cp_commit() {
    asm volatile("cp.async.commit_group;" ::: "memory");
}
__device__ __forceinline__ void ldm_x4(uint32_t* r, uint32_t addr) {
    asm volatile("ldmatrix.sync.aligned.m8n8.x4.shared.b16 {%0,%1,%2,%3}, [%4];"
                 : "=r"(r[0]), "=r"(r[1]), "=r"(r[2]), "=r"(r[3]) : "r"(addr));
}
__device__ __forceinline__ void ldm_x4_trans(uint32_t* r, uint32_t addr) {
    asm volatile("ldmatrix.sync.aligned.m8n8.x4.trans.shared.b16 {%0,%1,%2,%3}, [%4];"
                 : "=r"(r[0]), "=r"(r[1]), "=r"(r[2]), "=r"(r[3]) : "r"(addr));
}
__device__ __forceinline__ void mma_f16(float* c, const uint32_t* a, const uint32_t* b) {
    asm volatile(
        "mma.sync.aligned.m16n8k16.row.col.f32.f16.f16.f32 "
        "{%0,%1,%2,%3}, {%4,%5,%6,%7}, {%8,%9}, {%0,%1,%2,%3};"
        : "+f"(c[0]), "+f"(c[1]), "+f"(c[2]), "+f"(c[3])
        : "r"(a[0]), "r"(a[1]), "r"(a[2]), "r"(a[3]), "r"(b[0]), "r"(b[1]));
}
__device__ __forceinline__ void split2h(float a, float b, uint32_t& hi, uint32_t& lo) {
    __half2 h2 = __floats2half2_rn(a, b);
    float2 hf = __half22float2(h2);
    __half2 l2 = __floats2half2_rn(a - hf.x, b - hf.y);
    hi = *reinterpret_cast<uint32_t*>(&h2);
    lo = *reinterpret_cast<uint32_t*>(&l2);
}
__device__ __forceinline__ uint32_t pack2h(float a, float b) {
    __half2 h2 = __floats2half2_rn(a, b);
    return *reinterpret_cast<uint32_t*>(&h2);
}

// ---------------------------------------------------------------------------
// Fused pre-split: q_input (hi only) + 4 weights (hi+lo) in one launch.
// ---------------------------------------------------------------------------
__global__ __launch_bounds__(256) void split_all_kernel(
    const float* __restrict__ q_in,
    const float* __restrict__ WQ, const float* __restrict__ WK,
    const float* __restrict__ WV, const float* __restrict__ WO)
{
    const int blk = blockIdx.x;
    if (blk < 4096) {
        const int i = blk * 256 + threadIdx.x;
        float4 v = reinterpret_cast<const float4*>(q_in)[i];
        reinterpret_cast<uint2*>(g_qinh)[i] =
            make_uint2(pack2h(v.x, v.y), pack2h(v.z, v.w));
        return;
    }
    const int w = (blk - 4096) >> 10;
    const int i = ((blk - 4096) & 1023) * 256 + threadIdx.x;
    const float* src;
    __half *dh, *dl;
    switch (w) {
        case 0:  src = WQ; dh = g_wqh; dl = g_wql; break;
        case 1:  src = WK; dh = g_wkh; dl = g_wkl; break;
        case 2:  src = WV; dh = g_wvh; dl = g_wvl; break;
        default: src = WO; dh = g_woh; dl = g_wol; break;
    }
    float4 v = reinterpret_cast<const float4*>(src)[i];
    uint32_t h0, l0, h1, l1;
    split2h(v.x, v.y, h0, l0);
    split2h(v.z, v.w, h1, l1);
    reinterpret_cast<uint2*>(dh)[i] = make_uint2(h0, h1);
    reinterpret_cast<uint2*>(dl)[i] = make_uint2(l0, l1);
}

// ---------------------------------------------------------------------------
// Compaction scan: 1 block/batch, 1024 threads, 2 keys each.
// ---------------------------------------------------------------------------
__global__ __launch_bounds__(1024) void compact_scan_kernel(const int* __restrict__ mask)
{
    __shared__ int ssum[1024];
    const int b = blockIdx.x, t = threadIdx.x;
    const int* m = mask + (size_t)b * LK;
    const int f0 = (m[2 * t]     == 0) ? 1 : 0;
    const int f1 = (m[2 * t + 1] == 0) ? 1 : 0;
    ssum[t] = f0 + f1;
    __syncthreads();
    for (int off = 1; off < 1024; off <<= 1) {
        const int v = (t >= off) ? ssum[t - off] : 0;
        __syncthreads();
        ssum[t] += v;
        __syncthreads();
    }
    const int excl = ssum[t] - f0 - f1;
    if (f0) g_kidx[(size_t)b * LK + excl]      = 2 * t;
    if (f1) g_kidx[(size_t)b * LK + excl + f0] = 2 * t + 1;
    const int n = ssum[1023];
    if (t == 0) {
        g_nkv[b]  = n;
        g_npad[b] = (n + 127) & ~127;
    }
    g_biasc[(size_t)b * LK + 2 * t]     = (2 * t     < n) ? 0.0f : -1.0e30f;
    g_biasc[(size_t)b * LK + 2 * t + 1] = (2 * t + 1 < n) ? 0.0f : -1.0e30f;
}

// ---------------------------------------------------------------------------
// Fused gather + round: f32 kv rows -> compact fp16 (hi only; pads zeroed).
// ---------------------------------------------------------------------------
__global__ __launch_bounds__(256) void gather_split_kernel(const float* __restrict__ kv_in)
{
    const int b  = blockIdx.y;
    const int j0 = blockIdx.x * 8;
    const int n = g_nkv[b], npad = g_npad[b];
    if (j0 >= npad) return;
    const int tid = threadIdx.x;
    for (int i = tid; i < 8 * 256; i += 256) {
        const int r = i >> 8, c = i & 255;
        const int j = j0 + r;
        if (j >= npad) continue;
        uint2 uh = make_uint2(0, 0);
        if (j < n) {
            const int src = g_kidx[(size_t)b * LK + j];
            float4 v = reinterpret_cast<const float4*>(kv_in)
                           [((size_t)b * LK + src) * 256 + c];
            uh = make_uint2(pack2h(v.x, v.y), pack2h(v.z, v.w));
        }
        reinterpret_cast<uint2*>(g_ckinh)[((size_t)b * LK + j) * 256 + c] = uh;
    }
}

// ---------------------------------------------------------------------------
// GEMM core: 128x128 tile, BK=32, 256 thr, 2-stage cp.async, 2 CTAs/SM.
// 2-pass fp16: C = Ah*Bh + Ah*Bl.
// ---------------------------------------------------------------------------
#define G_STG 27648   // Ah 10240 + Bh 8704 + Bl 8704
#define GDSM  (2 * G_STG)

__device__ __forceinline__ void gemm_core(
    const __half* __restrict__ Ahg,
    const __half* __restrict__ Whg, const __half* __restrict__ Wlg,
    int brow, int bcol, char* dsm, float acc[4][4][4])
{
    const uint32_t sb = smem_u32(dsm);
    const int tid  = threadIdx.x;
    const int warp = tid >> 5, lane = tid & 31;
    const int wm   = warp >> 2, wn = warp & 3;

#pragma unroll
    for (int mi = 0; mi < 4; mi++)
#pragma unroll
        for (int ni = 0; ni < 4; ni++)
#pragma unroll
            for (int r = 0; r < 4; r++) acc[mi][ni][r] = 0.0f;

    auto issue = [&](int kt, int s) {
        const int k0 = kt * 32;
        const uint32_t st = sb + s * G_STG;
#pragma unroll
        for (int i = 0; i < 2; i++) {
            const int idx = i * 256 + tid;
            const int r = idx >> 2, c = idx & 3;
            cp16(st + r * 80 + c * 16,
                 Ahg + (size_t)(brow + r) * D_MODEL + k0 + c * 8);
        }
#pragma unroll
        for (int i = 0; i < 2; i++) {
            const int idx = i * 256 + tid;
            const int r = idx >> 4, c = idx & 15;
            const uint32_t d = st + 10240 + r * 272 + c * 16;
            const size_t go = (size_t)(k0 + r) * D_MODEL + bcol + c * 8;
            cp16(d,        Whg + go);
            cp16(d + 8704, Wlg + go);
        }
        cp_commit();
    };

    const int NK = D_MODEL / 32;
    issue(0, 0);
    for (int kt = 0; kt < NK; kt++) {
        const int s = kt & 1;
        if (kt + 1 < NK) {
            issue(kt + 1, s ^ 1);
            asm volatile("cp.async.wait_group 1;" ::: "memory");
        } else {
            asm volatile("cp.async.wait_group 0;" ::: "memory");
        }
        __syncthreads();

        const uint32_t ah = sb + s * G_STG;
        const uint32_t bh = ah + 10240;
        const uint32_t bl = ah + 18944;

#pragma unroll
        for (int ks = 0; ks < 2; ks++) {
            uint32_t afh[4][4], bfh[2][4], bfl[2][4];
#pragma unroll
            for (int mi = 0; mi < 4; mi++) {
                const int row = wm * 64 + mi * 16 + (lane & 15);
                const int col = ks * 16 + (lane >> 4) * 8;
                ldm_x4(afh[mi], ah + (uint32_t)(row * 40 + col) * 2);
            }
#pragma unroll
            for (int np = 0; np < 2; np++) {
                const int krow = ks * 16 + (lane & 15);
                const int ncol = wn * 32 + np * 16 + ((lane >> 4) & 1) * 8;
                const uint32_t off = (uint32_t)(krow * 136 + ncol) * 2;
                ldm_x4_trans(bfh[np], bh + off);
                ldm_x4_trans(bfl[np], bl + off);
            }
#pragma unroll
            for (int mi = 0; mi < 4; mi++)
#pragma unroll
                for (int ni = 0; ni < 4; ni++)
                    mma_f16(acc[mi][ni], afh[mi], &bfh[ni >> 1][(ni & 1) * 2]);
#pragma unroll
            for (int mi = 0; mi < 4; mi++)
#pragma unroll
                for (int ni = 0; ni < 4; ni++)
                    mma_f16(acc[mi][ni], afh[mi], &bfl[ni >> 1][(ni & 1) * 2]);
        }
        __syncthreads();
    }
}

// ---------------------------------------------------------------------------
// Fused Q + K + V projection GEMM. grid (16, 96).
// Q path: hi-only output (Cl == nullptr). K/V: split hi/lo.
// ---------------------------------------------------------------------------
__global__ __launch_bounds__(256, 2) void gemm_qkv(
    const float* __restrict__ bQ, const float* __restrict__ bK,
    const float* __restrict__ bV)
{
    extern __shared__ __align__(16) char dsm[];

    const __half *Ahg, *Whg, *Wlg;
    const float* bias;
    __half *Ch, *Cl;
    float scale;
    int brow, bx = blockIdx.x;

    if (blockIdx.y < 32) {
        if (bx >= 8) return;
        Ahg = g_qinh; Whg = g_wqh; Wlg = g_wql;
        bias = bQ; Ch = g_qh; Cl = nullptr; scale = 0.125f;
        brow = blockIdx.y * 128;
    } else {
        brow = (blockIdx.y - 32) * 128;
        const int bb = brow / LK;
        if ((brow % LK) >= g_npad[bb]) return;
        Ahg = g_ckinh; scale = 1.0f;
        if (bx < 8) { Whg = g_wkh; Wlg = g_wkl; bias = bK; Ch = g_kh; Cl = g_kl; }
        else { bx -= 8; Whg = g_wvh; Wlg = g_wvl; bias = bV; Ch = g_vh; Cl = g_vl; }
    }
    const int bcol = bx * 128;

    float acc[4][4][4];
    gemm_core(Ahg, Whg, Wlg, brow, bcol, dsm, acc);

    const int lane = threadIdx.x & 31, warp = threadIdx.x >> 5;
    const int wm = warp >> 2, wn = warp & 3;
    const int g = lane >> 2, t4 = lane & 3;
#pragma unroll
    for (int mi = 0; mi < 4; mi++) {
        const int row = brow + wm * 64 + mi * 16 + g;
#pragma unroll
        for (int ni = 0; ni < 4; ni++) {
            const int col = bcol + wn * 32 + ni * 8 + 2 * t4;
            const float b0 = bias[col], b1 = bias[col + 1];
            const float v0 = (acc[mi][ni][0] + b0) * scale;
            const float v1 = (acc[mi][ni][1] + b1) * scale;
            const float v2 = (acc[mi][ni][2] + b0) * scale;
            const float v3 = (acc[mi][ni][3] + b1) * scale;
            if (Cl != nullptr) {
                uint32_t h0, l0, h1, l1;
                split2h(v0, v1, h0, l0);
                split2h(v2, v3, h1, l1);
                *reinterpret_cast<uint32_t*>(&Ch[(size_t)row * D_MODEL + col])       = h0;
                *reinterpret_cast<uint32_t*>(&Cl[(size_t)row * D_MODEL + col])       = l0;
                *reinterpret_cast<uint32_t*>(&Ch[(size_t)(row + 8) * D_MODEL + col]) = h1;
                *reinterpret_cast<uint32_t*>(&Cl[(size_t)(row + 8) * D_MODEL + col]) = l1;
            } else {
                *reinterpret_cast<uint32_t*>(&Ch[(size_t)row * D_MODEL + col])       = pack2h(v0, v1);
                *reinterpret_cast<uint32_t*>(&Ch[(size_t)(row + 8) * D_MODEL + col]) = pack2h(v2, v3);
            }
        }
    }
}

// Output projection: fp32 out to d_out.
__global__ __launch_bounds__(256, 2) void gemm_o(
    const float* __restrict__ bO, float* __restrict__ C)
{
    extern __shared__ __align__(16) char dsm[];
    const int brow = blockIdx.y * 128;
    const int bcol = blockIdx.x * 128;

    float acc[4][4][4];
    gemm_core(g_ah, g_woh, g_wol, brow, bcol, dsm, acc);

    const int lane = threadIdx.x & 31, warp = threadIdx.x >> 5;
    const int wm = warp >> 2, wn = warp & 3;
    const int g = lane >> 2, t4 = lane & 3;
#pragma unroll
    for (int mi = 0; mi < 4; mi++) {
        const int row = brow + wm * 64 + mi * 16 + g;
#pragma unroll
        for (int ni = 0; ni < 4; ni++) {
            const int col = bcol + wn * 32 + ni * 8 + 2 * t4;
            const float b0 = bO[col], b1 = bO[col + 1];
            *reinterpret_cast<float2*>(C + (size_t)row * D_MODEL + col) =
                make_float2(acc[mi][ni][0] + b0, acc[mi][ni][1] + b1);
            *reinterpret_cast<float2*>(C + (size_t)(row + 8) * D_MODEL + col) =
                make_float2(acc[mi][ni][2] + b0, acc[mi][ni][3] + b1);
        }
    }
}

// ---------------------------------------------------------------------------
// fp16 tensor-core flash attention, 2-pass both phases:
//   S = Qh*(Kh+Kl),  O = Ph*(Vh+Vl)   (Q, P rounded to fp16)
// QT=64, 128 threads / 4 warps, 2 CTAs/SM, 2-stage cp.async pipeline.
// ---------------------------------------------------------------------------
#define A_TS   9216
#define A_STG  (4 * A_TS)
#define A_BOFF (2 * A_STG)
#define A_DSM  (A_BOFF + 512)

__global__ __launch_bounds__(128, 2) void attn_mma()
{
    extern __shared__ __align__(16) char dsm[];
    const uint32_t sb = smem_u32(dsm);

    const int tid  = threadIdx.x;
    const int warp = tid >> 5, lane = tid & 31;
    const int g    = lane >> 2, t4 = lane & 3;
    const int q0   = blockIdx.x * 64;
    const int h    = blockIdx.y;
    const int b    = blockIdx.z;
    const int NK   = g_npad[b] / 64;

    // ---- Q fragments (hi only) via stage-0 area ----
    uint32_t qfh[4][4];
    {
        const size_t qbase = ((size_t)b * LQ + q0) * D_MODEL + h * D_H;
#pragma unroll
        for (int i = 0; i < 4; i++) {
            const int idx = i * 128 + tid;
            const int r = idx >> 3, c = idx & 7;
            *reinterpret_cast<uint4*>(dsm + r * 144 + c * 16) =
                *reinterpret_cast<const uint4*>(g_qh + qbase + (size_t)r * D_MODEL + c * 8);
        }
        __syncthreads();
        const int rbase = warp * 16;
#pragma unroll
        for (int s = 0; s < 4; s++) {
            const uint32_t off =
                (uint32_t)((rbase + (lane & 15)) * 72 + (lane >> 4) * 8 + s * 16) * 2;
            ldm_x4(qfh[s], sb + off);
        }
        __syncthreads();
    }

    auto issue = [&](int kt, int s) {
        const size_t kvbase = ((size_t)b * LK + kt * 64) * D_MODEL + h * D_H;
        const uint32_t st = sb + s * A_STG;
#pragma unroll
        for (int i = 0; i < 16; i++) {
            const int tile = i >> 2;
            const int idx = (i & 3) * 128 + tid;
            const int r = idx >> 3, c = idx & 7;
            const size_t go = kvbase + (size_t)r * D_MODEL + c * 8;
            const uint32_t d = st + tile * A_TS + r * 144 + c * 16;
            const __half* src =
                tile == 0 ? g_kh : tile == 1 ? g_kl : tile == 2 ? g_vh : g_vl;
            cp16(d, src + go);
        }
        if (tid < 16)
            cp16(sb + A_BOFF + s * 256 + tid * 16,
                 g_biasc + (size_t)b * LK + kt * 64 + tid * 4);
        cp_commit();
    };

    float m0 = -1.0e30f, m1 = -1.0e30f, l0 = 0.0f, l1 = 0.0f;
    float o[8][4];
#pragma unroll
    for (int j = 0; j < 8; j++)
#pragma unroll
        for (int r = 0; r < 4; r++) o[j][r] = 0.0f;

    issue(0, 0);
    for (int kt = 0; kt < NK; kt++) {
        const int st = kt & 1;
        if (kt + 1 < NK) {
            issue(kt + 1, st ^ 1);
            asm volatile("cp.async.wait_group 1;" ::: "memory");
        } else {
            asm volatile("cp.async.wait_group 0;" ::: "memory");
        }
        __syncthreads();

        const uint32_t khb = sb + st * A_STG;
        const uint32_t klb = khb + A_TS;
        const uint32_t vhb = khb + 2 * A_TS;
        const uint32_t vlb = khb + 3 * A_TS;
        const float* bias_s = reinterpret_cast<const float*>(dsm + A_BOFF + st * 256);

        // ---- S = Qh K^T (2-pass: Kh then Kl) ----
        float s[8][4];
#pragma unroll
        for (int j = 0; j < 8; j++)
#pragma unroll
            for (int r = 0; r < 4; r++) s[j][r] = 0.0f;

#pragma unroll
        for (int ks = 0; ks < 4; ks++) {
#pragma unroll
            for (int jp2 = 0; jp2 < 2; jp2++) {
                uint32_t kh4[2][4], kl4[2][4];
#pragma unroll
                for (int q = 0; q < 2; q++) {
                    const int jp = jp2 * 2 + q;
                    const int row = jp * 16 + ((lane >> 4) & 1) * 8 + (lane & 7);
                    const int col = ks * 16 + ((lane >> 3) & 1) * 8;
                    const uint32_t off = (uint32_t)(row * 72 + col) * 2;
                    ldm_x4(kh4[q], khb + off);
                    ldm_x4(kl4[q], klb + off);
                }
#pragma unroll
                for (int q = 0; q < 2; q++) {
                    const int j0 = (jp2 * 2 + q) * 2;
                    mma_f16(s[j0],     qfh[ks], kh4[q]);
                    mma_f16(s[j0 + 1], qfh[ks], kh4[q] + 2);
                }
#pragma unroll
                for (int q = 0; q < 2; q++) {
                    const int j0 = (jp2 * 2 + q) * 2;
                    mma_f16(s[j0],     qfh[ks], kl4[q]);
                    mma_f16(s[j0 + 1], qfh[ks], kl4[q] + 2);
                }
            }
        }

        // ---- pad bias + online softmax ----
        float mx0 = -1.0e30f, mx1 = -1.0e30f;
#pragma unroll
        for (int j = 0; j < 8; j++) {
            const float b0 = bias_s[j * 8 + 2 * t4];
            const float b1 = bias_s[j * 8 + 2 * t4 + 1];
            s[j][0] += b0; s[j][1] += b1;
            s[j][2] += b0; s[j][3] += b1;
            mx0 = fmaxf(mx0, fmaxf(s[j][0], s[j][1]));
            mx1 = fmaxf(mx1, fmaxf(s[j][2], s[j][3]));
        }
        mx0 = fmaxf(mx0, __shfl_xor_sync(0xffffffffu, mx0, 1));
        mx0 = fmaxf(mx0, __shfl_xor_sync(0xffffffffu, mx0, 2));
        mx1 = fmaxf(mx1, __shfl_xor_sync(0xffffffffu, mx1, 1));
        mx1 = fmaxf(mx1, __shfl_xor_sync(0xffffffffu, mx1, 2));

        const float m0n = fmaxf(m0, mx0), m1n = fmaxf(m1, mx1);
        const float c0 = __expf(m0 - m0n), c1 = __expf(m1 - m1n);
        m0 = m0n; m1 = m1n;

        float sum0 = 0.0f, sum1 = 0.0f;
#pragma unroll
        for (int j = 0; j < 8; j++) {
            s[j][0] = __expf(s[j][0] - m0n);
            s[j][1] = __expf(s[j][1] - m0n);
            s[j][2] = __expf(s[j][2] - m1n);
            s[j][3] = __expf(s[j][3] - m1n);
            sum0 += s[j][0] + s[j][1];
            sum1 += s[j][2] + s[j][3];
        }
        sum0 += __shfl_xor_sync(0xffffffffu, sum0, 1);
        sum0 += __shfl_xor_sync(0xffffffffu, sum0, 2);
        sum1 += __shfl_xor_sync(0xffffffffu, sum1, 1);
        sum1 += __shfl_xor_sync(0xffffffffu, sum1, 2);
        l0 = l0 * c0 + sum0;
        l1 = l1 * c1 + sum1;

#pragma unroll
        for (int j = 0; j < 8; j++) {
            o[j][0] *= c0; o[j][1] *= c0;
            o[j][2] *= c1; o[j][3] *= c1;
        }

        // ---- O += Ph V (2-pass: Vh then Vl; P rounded to fp16) ----
#pragma unroll
        for (int ks = 0; ks < 4; ks++) {
            uint32_t pah[4];
            pah[0] = pack2h(s[2 * ks][0],     s[2 * ks][1]);
            pah[1] = pack2h(s[2 * ks][2],     s[2 * ks][3]);
            pah[2] = pack2h(s[2 * ks + 1][0], s[2 * ks + 1][1]);
            pah[3] = pack2h(s[2 * ks + 1][2], s[2 * ks + 1][3]);
#pragma unroll
            for (int jp2 = 0; jp2 < 2; jp2++) {
                uint32_t vh4[2][4], vl4[2][4];
#pragma unroll
                for (int q = 0; q < 2; q++) {
                    const int jp = jp2 * 2 + q;
                    const int row = ks * 16 + (lane & 15);
                    const int col = jp * 16 + ((lane >> 4) & 1) * 8;
                    const uint32_t off = (uint32_t)(row * 72 + col) * 2;
                    ldm_x4_trans(vh4[q], vhb + off);
                    ldm_x4_trans(vl4[q], vlb + off);
                }
#pragma unroll
                for (int q = 0; q < 2; q++) {
                    const int j0 = (jp2 * 2 + q) * 2;
                    mma_f16(o[j0],     pah, vh4[q]);
                    mma_f16(o[j0 + 1], pah, vh4[q] + 2);
                }
#pragma unroll
                for (int q = 0; q < 2; q++) {
                    const int j0 = (jp2 * 2 + q) * 2;
                    mma_f16(o[j0],     pah, vl4[q]);
                    mma_f16(o[j0 + 1], pah, vl4[q] + 2);
                }
            }
        }
        __syncthreads();
    }

    // ---- normalize + write single-fp16 output ----
    const float li0 = 1.0f / l0, li1 = 1.0f / l1;
    const int row0 = q0 + warp * 16 + g;
    const size_t base0 = ((size_t)b * LQ + row0) * D_MODEL + h * D_H;
    const size_t base1 = base0 + (size_t)8 * D_MODEL;
#pragma unroll
    for (int j = 0; j < 8; j++) {
        const int col = j * 8 + 2 * t4;
        *reinterpret_cast<uint32_t*>(&g_ah[base0 + col]) =
            pack2h(o[j][0] * li0, o[j][1] * li0);
        *reinterpret_cast<uint32_t*>(&g_ah[base1 + col]) =
            pack2h(o[j][2] * li1, o[j][3] * li1);
    }
}

// ---------------------------------------------------------------------------
// Launch
// ---------------------------------------------------------------------------
extern "C" void kernel_launch(void* const* d_in, const int* in_sizes, int n_in,
                              void* d_out, int out_size)
{
    const float* q_in  = (const float*)d_in[0];
    const float* kv_in = (const float*)d_in[1];
    const int*   mask  = (const int*)  d_in[2];
    const float* W_Q   = (const float*)d_in[3];
    const float* b_Q   = (const float*)d_in[4];
    const float* W_K   = (const float*)d_in[5];
    const float* b_K   = (const float*)d_in[6];
    const float* W_V   = (const float*)d_in[7];
    const float* b_V   = (const float*)d_in[8];
    const float* W_O   = (const float*)d_in[9];
    const float* b_O   = (const float*)d_in[10];

    cudaFuncSetAttribute(gemm_qkv, cudaFuncAttributeMaxDynamicSharedMemorySize, GDSM);
    cudaFuncSetAttribute(gemm_o,   cudaFuncAttributeMaxDynamicSharedMemorySize, GDSM);
    cudaFuncSetAttribute(attn_mma, cudaFuncAttributeMaxDynamicSharedMemorySize, A_DSM);

    // ---- preprocessing: splits + compaction ----
    split_all_kernel<<<8192, 256>>>(q_in, W_Q, W_K, W_V, W_O);
    compact_scan_kernel<<<BATCH, 1024>>>(mask);
    gather_split_kernel<<<dim3(LK / 8, BATCH), 256>>>(kv_in);

    // ---- fused Q/K/V projections ----
    gemm_qkv<<<dim3(16, 96), 256, GDSM>>>(b_Q, b_K, b_V);

    // ---- attention over compacted keys ----
    attn_mma<<<dim3(LQ / 64, N_HEAD, BATCH), 128, A_DSM>>>();

    // ---- output projection ----
    gemm_o<<<dim3(8, 32), 256, GDSM>>>(b_O, (float*)d_out);
}

// round 14
// speedup vs baseline: 1.7515x; 1.2171x over previous
#include <cuda_runtime.h>
#include <cuda_fp16.h>
#include <stdint.h>
#include <math.h>

#define D_MODEL 1024
#define N_HEAD  16
#define D_H     64
#define BATCH   4
#define LQ      1024
#define LK      2048

// ---------------------------------------------------------------------------
// Scratch (no cudaMalloc allowed)
// ---------------------------------------------------------------------------
__device__ __half g_qinh [(size_t)BATCH * LQ * D_MODEL];   // fp16 activation
__device__ __half g_ckinh[(size_t)BATCH * LK * D_MODEL];   // compacted kv input
__device__ __half g_wqh[(size_t)D_MODEL * D_MODEL];
__device__ __half g_wkh[(size_t)D_MODEL * D_MODEL];
__device__ __half g_wkl[(size_t)D_MODEL * D_MODEL];
__device__ __half g_wvh[(size_t)D_MODEL * D_MODEL];
__device__ __half g_wvl[(size_t)D_MODEL * D_MODEL];
__device__ __half g_woh[(size_t)D_MODEL * D_MODEL];
__device__ __half g_wol[(size_t)D_MODEL * D_MODEL];
// projections: all fp16 hi-only (1-pass attention)
__device__ __half g_qh[(size_t)BATCH * LQ * D_MODEL];
__device__ __half g_kh[(size_t)BATCH * LK * D_MODEL];
__device__ __half g_vh[(size_t)BATCH * LK * D_MODEL];
// attention output: single fp16
__device__ __half g_ah[(size_t)BATCH * LQ * D_MODEL];
// compaction metadata
__device__ int   g_kidx[(size_t)BATCH * LK];
__device__ int   g_nkv[BATCH];
__device__ int   g_npad[BATCH];
__device__ float g_biasc[(size_t)BATCH * LK];

// ---------------------------------------------------------------------------
// Helpers
// ---------------------------------------------------------------------------
__device__ __forceinline__ uint32_t smem_u32(const void* p) {
    uint32_t a;
    asm("{ .reg .u64 t; cvta.to.shared.u64 t, %1; cvt.u32.u64 %0, t; }"
        : "=r"(a) : "l"(p));
    return a;
}
__device__ __forceinline__ void cp16(uint32_t d, const void* g) {
    asm volatile("cp.async.cg.shared.global [%0], [%1], 16;" :: "r"(d), "l"(g));
}
__device__ __forceinline__ void cp_commit() {
    asm volatile("cp.async.commit_group;" ::: "memory");
}
__device__ __forceinline__ void ldm_x4(uint32_t* r, uint32_t addr) {
    asm volatile("ldmatrix.sync.aligned.m8n8.x4.shared.b16 {%0,%1,%2,%3}, [%4];"
                 : "=r"(r[0]), "=r"(r[1]), "=r"(r[2]), "=r"(r[3]) : "r"(addr));
}
__device__ __forceinline__ void ldm_x4_trans(uint32_t* r, uint32_t addr) {
    asm volatile("ldmatrix.sync.aligned.m8n8.x4.trans.shared.b16 {%0,%1,%2,%3}, [%4];"
                 : "=r"(r[0]), "=r"(r[1]), "=r"(r[2]), "=r"(r[3]) : "r"(addr));
}
__device__ __forceinline__ void mma_f16(float* c, const uint32_t* a, const uint32_t* b) {
    asm volatile(
        "mma.sync.aligned.m16n8k16.row.col.f32.f16.f16.f32 "
        "{%0,%1,%2,%3}, {%4,%5,%6,%7}, {%8,%9}, {%0,%1,%2,%3};"
        : "+f"(c[0]), "+f"(c[1]), "+f"(c[2]), "+f"(c[3])
        : "r"(a[0]), "r"(a[1]), "r"(a[2]), "r"(a[3]), "r"(b[0]), "r"(b[1]));
}
__device__ __forceinline__ void split2h(float a, float b, uint32_t& hi, uint32_t& lo) {
    __half2 h2 = __floats2half2_rn(a, b);
    float2 hf = __half22float2(h2);
    __half2 l2 = __floats2half2_rn(a - hf.x, b - hf.y);
    hi = *reinterpret_cast<uint32_t*>(&h2);
    lo = *reinterpret_cast<uint32_t*>(&l2);
}
__device__ __forceinline__ uint32_t pack2h(float a, float b) {
    __half2 h2 = __floats2half2_rn(a, b);
    return *reinterpret_cast<uint32_t*>(&h2);
}

// ---------------------------------------------------------------------------
// Fused pre-split: q_input + W_Q (hi only); W_K/W_V/W_O (hi+lo).
// blocks [0,4096): q_in; [4096,8192): weights (1024 each).
// ---------------------------------------------------------------------------
__global__ __launch_bounds__(256) void split_all_kernel(
    const float* __restrict__ q_in,
    const float* __restrict__ WQ, const float* __restrict__ WK,
    const float* __restrict__ WV, const float* __restrict__ WO)
{
    const int blk = blockIdx.x;
    if (blk < 4096) {
        const int i = blk * 256 + threadIdx.x;
        float4 v = reinterpret_cast<const float4*>(q_in)[i];
        reinterpret_cast<uint2*>(g_qinh)[i] =
            make_uint2(pack2h(v.x, v.y), pack2h(v.z, v.w));
        return;
    }
    const int w = (blk - 4096) >> 10;
    const int i = ((blk - 4096) & 1023) * 256 + threadIdx.x;
    if (w == 0) {   // W_Q: hi only (1-pass Q projection)
        float4 v = reinterpret_cast<const float4*>(WQ)[i];
        reinterpret_cast<uint2*>(g_wqh)[i] =
            make_uint2(pack2h(v.x, v.y), pack2h(v.z, v.w));
        return;
    }
    const float* src;
    __half *dh, *dl;
    switch (w) {
        case 1:  src = WK; dh = g_wkh; dl = g_wkl; break;
        case 2:  src = WV; dh = g_wvh; dl = g_wvl; break;
        default: src = WO; dh = g_woh; dl = g_wol; break;
    }
    float4 v = reinterpret_cast<const float4*>(src)[i];
    uint32_t h0, l0, h1, l1;
    split2h(v.x, v.y, h0, l0);
    split2h(v.z, v.w, h1, l1);
    reinterpret_cast<uint2*>(dh)[i] = make_uint2(h0, h1);
    reinterpret_cast<uint2*>(dl)[i] = make_uint2(l0, l1);
}

// ---------------------------------------------------------------------------
// Compaction scan: 1 block/batch, 1024 threads, 2 keys each.
// ---------------------------------------------------------------------------
__global__ __launch_bounds__(1024) void compact_scan_kernel(const int* __restrict__ mask)
{
    __shared__ int ssum[1024];
    const int b = blockIdx.x, t = threadIdx.x;
    const int* m = mask + (size_t)b * LK;
    const int f0 = (m[2 * t]     == 0) ? 1 : 0;
    const int f1 = (m[2 * t + 1] == 0) ? 1 : 0;
    ssum[t] = f0 + f1;
    __syncthreads();
    for (int off = 1; off < 1024; off <<= 1) {
        const int v = (t >= off) ? ssum[t - off] : 0;
        __syncthreads();
        ssum[t] += v;
        __syncthreads();
    }
    const int excl = ssum[t] - f0 - f1;
    if (f0) g_kidx[(size_t)b * LK + excl]      = 2 * t;
    if (f1) g_kidx[(size_t)b * LK + excl + f0] = 2 * t + 1;
    const int n = ssum[1023];
    if (t == 0) {
        g_nkv[b]  = n;
        g_npad[b] = (n + 127) & ~127;
    }
    g_biasc[(size_t)b * LK + 2 * t]     = (2 * t     < n) ? 0.0f : -1.0e30f;
    g_biasc[(size_t)b * LK + 2 * t + 1] = (2 * t + 1 < n) ? 0.0f : -1.0e30f;
}

// ---------------------------------------------------------------------------
// Fused gather + round: f32 kv rows -> compact fp16 (pads zeroed).
// ---------------------------------------------------------------------------
__global__ __launch_bounds__(256) void gather_split_kernel(const float* __restrict__ kv_in)
{
    const int b  = blockIdx.y;
    const int j0 = blockIdx.x * 8;
    const int n = g_nkv[b], npad = g_npad[b];
    if (j0 >= npad) return;
    const int tid = threadIdx.x;
    for (int i = tid; i < 8 * 256; i += 256) {
        const int r = i >> 8, c = i & 255;
        const int j = j0 + r;
        if (j >= npad) continue;
        uint2 uh = make_uint2(0, 0);
        if (j < n) {
            const int src = g_kidx[(size_t)b * LK + j];
            float4 v = reinterpret_cast<const float4*>(kv_in)
                           [((size_t)b * LK + src) * 256 + c];
            uh = make_uint2(pack2h(v.x, v.y), pack2h(v.z, v.w));
        }
        reinterpret_cast<uint2*>(g_ckinh)[((size_t)b * LK + j) * 256 + c] = uh;
    }
}

// ---------------------------------------------------------------------------
// GEMM core: 128x128 tile, BK=32, 256 thr, 2-stage cp.async, 2 CTAs/SM.
// Wlg == nullptr -> 1-pass (C = Ah*Bh); else 2-pass (C = Ah*Bh + Ah*Bl).
// ---------------------------------------------------------------------------
#define G_STG 27648   // Ah 10240 + Bh 8704 + Bl 8704
#define GDSM  (2 * G_STG)

__device__ __forceinline__ void gemm_core(
    const __half* __restrict__ Ahg,
    const __half* __restrict__ Whg, const __half* __restrict__ Wlg,
    int brow, int bcol, char* dsm, float acc[4][4][4])
{
    const uint32_t sb = smem_u32(dsm);
    const int tid  = threadIdx.x;
    const int warp = tid >> 5, lane = tid & 31;
    const int wm   = warp >> 2, wn = warp & 3;
    const bool two = (Wlg != nullptr);

#pragma unroll
    for (int mi = 0; mi < 4; mi++)
#pragma unroll
        for (int ni = 0; ni < 4; ni++)
#pragma unroll
            for (int r = 0; r < 4; r++) acc[mi][ni][r] = 0.0f;

    auto issue = [&](int kt, int s) {
        const int k0 = kt * 32;
        const uint32_t st = sb + s * G_STG;
#pragma unroll
        for (int i = 0; i < 2; i++) {
            const int idx = i * 256 + tid;
            const int r = idx >> 2, c = idx & 3;
            cp16(st + r * 80 + c * 16,
                 Ahg + (size_t)(brow + r) * D_MODEL + k0 + c * 8);
        }
#pragma unroll
        for (int i = 0; i < 2; i++) {
            const int idx = i * 256 + tid;
            const int r = idx >> 4, c = idx & 15;
            const uint32_t d = st + 10240 + r * 272 + c * 16;
            const size_t go = (size_t)(k0 + r) * D_MODEL + bcol + c * 8;
            cp16(d, Whg + go);
            if (two) cp16(d + 8704, Wlg + go);
        }
        cp_commit();
    };

    const int NK = D_MODEL / 32;
    issue(0, 0);
    for (int kt = 0; kt < NK; kt++) {
        const int s = kt & 1;
        if (kt + 1 < NK) {
            issue(kt + 1, s ^ 1);
            asm volatile("cp.async.wait_group 1;" ::: "memory");
        } else {
            asm volatile("cp.async.wait_group 0;" ::: "memory");
        }
        __syncthreads();

        const uint32_t ah = sb + s * G_STG;
        const uint32_t bh = ah + 10240;
        const uint32_t bl = ah + 18944;

#pragma unroll
        for (int ks = 0; ks < 2; ks++) {
            uint32_t afh[4][4], bfh[2][4];
#pragma unroll
            for (int mi = 0; mi < 4; mi++) {
                const int row = wm * 64 + mi * 16 + (lane & 15);
                const int col = ks * 16 + (lane >> 4) * 8;
                ldm_x4(afh[mi], ah + (uint32_t)(row * 40 + col) * 2);
            }
#pragma unroll
            for (int np = 0; np < 2; np++) {
                const int krow = ks * 16 + (lane & 15);
                const int ncol = wn * 32 + np * 16 + ((lane >> 4) & 1) * 8;
                ldm_x4_trans(bfh[np], bh + (uint32_t)(krow * 136 + ncol) * 2);
            }
#pragma unroll
            for (int mi = 0; mi < 4; mi++)
#pragma unroll
                for (int ni = 0; ni < 4; ni++)
                    mma_f16(acc[mi][ni], afh[mi], &bfh[ni >> 1][(ni & 1) * 2]);
            if (two) {
                uint32_t bfl[2][4];
#pragma unroll
                for (int np = 0; np < 2; np++) {
                    const int krow = ks * 16 + (lane & 15);
                    const int ncol = wn * 32 + np * 16 + ((lane >> 4) & 1) * 8;
                    ldm_x4_trans(bfl[np], bl + (uint32_t)(krow * 136 + ncol) * 2);
                }
#pragma unroll
                for (int mi = 0; mi < 4; mi++)
#pragma unroll
                    for (int ni = 0; ni < 4; ni++)
                        mma_f16(acc[mi][ni], afh[mi], &bfl[ni >> 1][(ni & 1) * 2]);
            }
        }
        __syncthreads();
    }
}

// ---------------------------------------------------------------------------
// Fused Q + K + V projection GEMM. grid (16, 96). All outputs fp16 hi-only.
// Q path: 1-pass (Wl = nullptr). K/V: 2-pass.
// ---------------------------------------------------------------------------
__global__ __launch_bounds__(256, 2) void gemm_qkv(
    const float* __restrict__ bQ, const float* __restrict__ bK,
    const float* __restrict__ bV)
{
    extern __shared__ __align__(16) char dsm[];

    const __half *Ahg, *Whg, *Wlg;
    const float* bias;
    __half* Ch;
    float scale;
    int brow, bx = blockIdx.x;

    if (blockIdx.y < 32) {
        if (bx >= 8) return;
        Ahg = g_qinh; Whg = g_wqh; Wlg = nullptr;
        bias = bQ; Ch = g_qh; scale = 0.125f;
        brow = blockIdx.y * 128;
    } else {
        brow = (blockIdx.y - 32) * 128;
        const int bb = brow / LK;
        if ((brow % LK) >= g_npad[bb]) return;
        Ahg = g_ckinh; scale = 1.0f;
        if (bx < 8) { Whg = g_wkh; Wlg = g_wkl; bias = bK; Ch = g_kh; }
        else { bx -= 8; Whg = g_wvh; Wlg = g_wvl; bias = bV; Ch = g_vh; }
    }
    const int bcol = bx * 128;

    float acc[4][4][4];
    gemm_core(Ahg, Whg, Wlg, brow, bcol, dsm, acc);

    const int lane = threadIdx.x & 31, warp = threadIdx.x >> 5;
    const int wm = warp >> 2, wn = warp & 3;
    const int g = lane >> 2, t4 = lane & 3;
#pragma unroll
    for (int mi = 0; mi < 4; mi++) {
        const int row = brow + wm * 64 + mi * 16 + g;
#pragma unroll
        for (int ni = 0; ni < 4; ni++) {
            const int col = bcol + wn * 32 + ni * 8 + 2 * t4;
            const float b0 = bias[col], b1 = bias[col + 1];
            *reinterpret_cast<uint32_t*>(&Ch[(size_t)row * D_MODEL + col]) =
                pack2h((acc[mi][ni][0] + b0) * scale, (acc[mi][ni][1] + b1) * scale);
            *reinterpret_cast<uint32_t*>(&Ch[(size_t)(row + 8) * D_MODEL + col]) =
                pack2h((acc[mi][ni][2] + b0) * scale, (acc[mi][ni][3] + b1) * scale);
        }
    }
}

// Output projection: 2-pass, fp32 out to d_out.
__global__ __launch_bounds__(256, 2) void gemm_o(
    const float* __restrict__ bO, float* __restrict__ C)
{
    extern __shared__ __align__(16) char dsm[];
    const int brow = blockIdx.y * 128;
    const int bcol = blockIdx.x * 128;

    float acc[4][4][4];
    gemm_core(g_ah, g_woh, g_wol, brow, bcol, dsm, acc);

    const int lane = threadIdx.x & 31, warp = threadIdx.x >> 5;
    const int wm = warp >> 2, wn = warp & 3;
    const int g = lane >> 2, t4 = lane & 3;
#pragma unroll
    for (int mi = 0; mi < 4; mi++) {
        const int row = brow + wm * 64 + mi * 16 + g;
#pragma unroll
        for (int ni = 0; ni < 4; ni++) {
            const int col = bcol + wn * 32 + ni * 8 + 2 * t4;
            const float b0 = bO[col], b1 = bO[col + 1];
            *reinterpret_cast<float2*>(C + (size_t)row * D_MODEL + col) =
                make_float2(acc[mi][ni][0] + b0, acc[mi][ni][1] + b1);
            *reinterpret_cast<float2*>(C + (size_t)(row + 8) * D_MODEL + col) =
                make_float2(acc[mi][ni][2] + b0, acc[mi][ni][3] + b1);
        }
    }
}

// ---------------------------------------------------------------------------
// Pure-fp16 tensor-core flash attention (1-pass): S = Qh*Kh, O = Ph*Vh.
// QT=64, 128 threads / 4 warps, 3 CTAs/SM, 2-stage cp.async pipeline.
// ---------------------------------------------------------------------------
#define A_TS   9216
#define A_STG  (2 * A_TS)     // Kh, Vh
#define A_BOFF (2 * A_STG)    // 36864
#define A_DSM  (A_BOFF + 512)

__global__ __launch_bounds__(128, 3) void attn_mma()
{
    extern __shared__ __align__(16) char dsm[];
    const uint32_t sb = smem_u32(dsm);

    const int tid  = threadIdx.x;
    const int warp = tid >> 5, lane = tid & 31;
    const int g    = lane >> 2, t4 = lane & 3;
    const int q0   = blockIdx.x * 64;
    const int h    = blockIdx.y;
    const int b    = blockIdx.z;
    const int NK   = g_npad[b] / 64;

    // ---- Q fragments via stage-0 area ----
    uint32_t qfh[4][4];
    {
        const size_t qbase = ((size_t)b * LQ + q0) * D_MODEL + h * D_H;
#pragma unroll
        for (int i = 0; i < 4; i++) {
            const int idx = i * 128 + tid;
            const int r = idx >> 3, c = idx & 7;
            *reinterpret_cast<uint4*>(dsm + r * 144 + c * 16) =
                *reinterpret_cast<const uint4*>(g_qh + qbase + (size_t)r * D_MODEL + c * 8);
        }
        __syncthreads();
        const int rbase = warp * 16;
#pragma unroll
        for (int s = 0; s < 4; s++) {
            const uint32_t off =
                (uint32_t)((rbase + (lane & 15)) * 72 + (lane >> 4) * 8 + s * 16) * 2;
            ldm_x4(qfh[s], sb + off);
        }
        __syncthreads();
    }

    auto issue = [&](int kt, int s) {
        const size_t kvbase = ((size_t)b * LK + kt * 64) * D_MODEL + h * D_H;
        const uint32_t st = sb + s * A_STG;
#pragma unroll
        for (int i = 0; i < 8; i++) {
            const int tile = i >> 2;                 // 0: Kh, 1: Vh
            const int idx = (i & 3) * 128 + tid;
            const int r = idx >> 3, c = idx & 7;
            const size_t go = kvbase + (size_t)r * D_MODEL + c * 8;
            const uint32_t d = st + tile * A_TS + r * 144 + c * 16;
            cp16(d, (tile == 0 ? g_kh : g_vh) + go);
        }
        if (tid < 16)
            cp16(sb + A_BOFF + s * 256 + tid * 16,
                 g_biasc + (size_t)b * LK + kt * 64 + tid * 4);
        cp_commit();
    };

    float m0 = -1.0e30f, m1 = -1.0e30f, l0 = 0.0f, l1 = 0.0f;
    float o[8][4];
#pragma unroll
    for (int j = 0; j < 8; j++)
#pragma unroll
        for (int r = 0; r < 4; r++) o[j][r] = 0.0f;

    issue(0, 0);
    for (int kt = 0; kt < NK; kt++) {
        const int st = kt & 1;
        if (kt + 1 < NK) {
            issue(kt + 1, st ^ 1);
            asm volatile("cp.async.wait_group 1;" ::: "memory");
        } else {
            asm volatile("cp.async.wait_group 0;" ::: "memory");
        }
        __syncthreads();

        const uint32_t khb = sb + st * A_STG;
        const uint32_t vhb = khb + A_TS;
        const float* bias_s = reinterpret_cast<const float*>(dsm + A_BOFF + st * 256);

        // ---- S = Qh Kh^T (1-pass) ----
        float s[8][4];
#pragma unroll
        for (int j = 0; j < 8; j++)
#pragma unroll
            for (int r = 0; r < 4; r++) s[j][r] = 0.0f;

#pragma unroll
        for (int ks = 0; ks < 4; ks++) {
#pragma unroll
            for (int jp2 = 0; jp2 < 2; jp2++) {
                uint32_t kh4[2][4];
#pragma unroll
                for (int q = 0; q < 2; q++) {
                    const int jp = jp2 * 2 + q;
                    const int row = jp * 16 + ((lane >> 4) & 1) * 8 + (lane & 7);
                    const int col = ks * 16 + ((lane >> 3) & 1) * 8;
                    ldm_x4(kh4[q], khb + (uint32_t)(row * 72 + col) * 2);
                }
#pragma unroll
                for (int q = 0; q < 2; q++) {
                    const int j0 = (jp2 * 2 + q) * 2;
                    mma_f16(s[j0],     qfh[ks], kh4[q]);
                    mma_f16(s[j0 + 1], qfh[ks], kh4[q] + 2);
                }
            }
        }

        // ---- pad bias + online softmax ----
        float mx0 = -1.0e30f, mx1 = -1.0e30f;
#pragma unroll
        for (int j = 0; j < 8; j++) {
            const float b0 = bias_s[j * 8 + 2 * t4];
            const float b1 = bias_s[j * 8 + 2 * t4 + 1];
            s[j][0] += b0; s[j][1] += b1;
            s[j][2] += b0; s[j][3] += b1;
            mx0 = fmaxf(mx0, fmaxf(s[j][0], s[j][1]));
            mx1 = fmaxf(mx1, fmaxf(s[j][2], s[j][3]));
        }
        mx0 = fmaxf(mx0, __shfl_xor_sync(0xffffffffu, mx0, 1));
        mx0 = fmaxf(mx0, __shfl_xor_sync(0xffffffffu, mx0, 2));
        mx1 = fmaxf(mx1, __shfl_xor_sync(0xffffffffu, mx1, 1));
        mx1 = fmaxf(mx1, __shfl_xor_sync(0xffffffffu, mx1, 2));

        const float m0n = fmaxf(m0, mx0), m1n = fmaxf(m1, mx1);
        const float c0 = __expf(m0 - m0n), c1 = __expf(m1 - m1n);
        m0 = m0n; m1 = m1n;

        float sum0 = 0.0f, sum1 = 0.0f;
#pragma unroll
        for (int j = 0; j < 8; j++) {
            s[j][0] = __expf(s[j][0] - m0n);
            s[j][1] = __expf(s[j][1] - m0n);
            s[j][2] = __expf(s[j][2] - m1n);
            s[j][3] = __expf(s[j][3] - m1n);
            sum0 += s[j][0] + s[j][1];
            sum1 += s[j][2] + s[j][3];
        }
        sum0 += __shfl_xor_sync(0xffffffffu, sum0, 1);
        sum0 += __shfl_xor_sync(0xffffffffu, sum0, 2);
        sum1 += __shfl_xor_sync(0xffffffffu, sum1, 1);
        sum1 += __shfl_xor_sync(0xffffffffu, sum1, 2);
        l0 = l0 * c0 + sum0;
        l1 = l1 * c1 + sum1;

#pragma unroll
        for (int j = 0; j < 8; j++) {
            o[j][0] *= c0; o[j][1] *= c0;
            o[j][2] *= c1; o[j][3] *= c1;
        }

        // ---- O += Ph Vh (1-pass) ----
#pragma unroll
        for (int ks = 0; ks < 4; ks++) {
            uint32_t pah[4];
            pah[0] = pack2h(s[2 * ks][0],     s[2 * ks][1]);
            pah[1] = pack2h(s[2 * ks][2],     s[2 * ks][3]);
            pah[2] = pack2h(s[2 * ks + 1][0], s[2 * ks + 1][1]);
            pah[3] = pack2h(s[2 * ks + 1][2], s[2 * ks + 1][3]);
#pragma unroll
            for (int jp2 = 0; jp2 < 2; jp2++) {
                uint32_t vh4[2][4];
#pragma unroll
                for (int q = 0; q < 2; q++) {
                    const int jp = jp2 * 2 + q;
                    const int row = ks * 16 + (lane & 15);
                    const int col = jp * 16 + ((lane >> 4) & 1) * 8;
                    ldm_x4_trans(vh4[q], vhb + (uint32_t)(row * 72 + col) * 2);
                }
#pragma unroll
                for (int q = 0; q < 2; q++) {
                    const int j0 = (jp2 * 2 + q) * 2;
                    mma_f16(o[j0],     pah, vh4[q]);
                    mma_f16(o[j0 + 1], pah, vh4[q] + 2);
                }
            }
        }
        __syncthreads();
    }

    // ---- normalize + write fp16 output ----
    const float li0 = 1.0f / l0, li1 = 1.0f / l1;
    const int row0 = q0 + warp * 16 + g;
    const size_t base0 = ((size_t)b * LQ + row0) * D_MODEL + h * D_H;
    const size_t base1 = base0 + (size_t)8 * D_MODEL;
#pragma unroll
    for (int j = 0; j < 8; j++) {
        const int col = j * 8 + 2 * t4;
        *reinterpret_cast<uint32_t*>(&g_ah[base0 + col]) =
            pack2h(o[j][0] * li0, o[j][1] * li0);
        *reinterpret_cast<uint32_t*>(&g_ah[base1 + col]) =
            pack2h(o[j][2] * li1, o[j][3] * li1);
    }
}

// ---------------------------------------------------------------------------
// Launch
// ---------------------------------------------------------------------------
extern "C" void kernel_launch(void* const* d_in, const int* in_sizes, int n_in,
                              void* d_out, int out_size)
{
    const float* q_in  = (const float*)d_in[0];
    const float* kv_in = (const float*)d_in[1];
    const int*   mask  = (const int*)  d_in[2];
    const float* W_Q   = (const float*)d_in[3];
    const float* b_Q   = (const float*)d_in[4];
    const float* W_K   = (const float*)d_in[5];
    const float* b_K   = (const float*)d_in[6];
    const float* W_V   = (const float*)d_in[7];
    const float* b_V   = (const float*)d_in[8];
    const float* W_O   = (const float*)d_in[9];
    const float* b_O   = (const float*)d_in[10];

    cudaFuncSetAttribute(gemm_qkv, cudaFuncAttributeMaxDynamicSharedMemorySize, GDSM);
    cudaFuncSetAttribute(gemm_o,   cudaFuncAttributeMaxDynamicSharedMemorySize, GDSM);
    cudaFuncSetAttribute(attn_mma, cudaFuncAttributeMaxDynamicSharedMemorySize, A_DSM);

    // ---- preprocessing: splits + compaction ----
    split_all_kernel<<<8192, 256>>>(q_in, W_Q, W_K, W_V, W_O);
    compact_scan_kernel<<<BATCH, 1024>>>(mask);
    gather_split_kernel<<<dim3(LK / 8, BATCH), 256>>>(kv_in);

    // ---- fused Q/K/V projections ----
    gemm_qkv<<<dim3(16, 96), 256, GDSM>>>(b_Q, b_K, b_V);

    // ---- attention over compacted keys ----
    attn_mma<<<dim3(LQ / 64, N_HEAD, BATCH), 128, A_DSM>>>();

    // ---- output projection ----
    gemm_o<<<dim3(8, 32), 256, GDSM>>>(b_O, (float*)d_out);
}

// round 16
// speedup vs baseline: 2.1989x; 1.2554x over previous
#include <cuda_runtime.h>
#include <cuda_fp16.h>
#include <stdint.h>
#include <math.h>

#define D_MODEL 1024
#define N_HEAD  16
#define D_H     64
#define BATCH   4
#define LQ      1024
#define LK      2048

// ---------------------------------------------------------------------------
// Scratch (no cudaMalloc allowed) — pure fp16 pipeline
// ---------------------------------------------------------------------------
__device__ __half g_qinh [(size_t)BATCH * LQ * D_MODEL];
__device__ __half g_ckinh[(size_t)BATCH * LK * D_MODEL];
__device__ __half g_wqh[(size_t)D_MODEL * D_MODEL];
__device__ __half g_wkh[(size_t)D_MODEL * D_MODEL];
__device__ __half g_wvh[(size_t)D_MODEL * D_MODEL];
__device__ __half g_woh[(size_t)D_MODEL * D_MODEL];
__device__ __half g_qh[(size_t)BATCH * LQ * D_MODEL];
__device__ __half g_kh[(size_t)BATCH * LK * D_MODEL];
__device__ __half g_vh[(size_t)BATCH * LK * D_MODEL];
__device__ __half g_ah[(size_t)BATCH * LQ * D_MODEL];
// compaction metadata
__device__ int   g_kidx[(size_t)BATCH * LK];
__device__ int   g_nkv[BATCH];
__device__ int   g_npad[BATCH];
__device__ float g_biasc[(size_t)BATCH * LK];

// ---------------------------------------------------------------------------
// Helpers
// ---------------------------------------------------------------------------
__device__ __forceinline__ uint32_t smem_u32(const void* p) {
    uint32_t a;
    asm("{ .reg .u64 t; cvta.to.shared.u64 t, %1; cvt.u32.u64 %0, t; }"
        : "=r"(a) : "l"(p));
    return a;
}
__device__ __forceinline__ void cp16(uint32_t d, const void* g) {
    asm volatile("cp.async.cg.shared.global [%0], [%1], 16;" :: "r"(d), "l"(g));
}
__device__ __forceinline__ void cp_commit() {
    asm volatile("cp.async.commit_group;" ::: "memory");
}
__device__ __forceinline__ void ldm_x4(uint32_t* r, uint32_t addr) {
    asm volatile("ldmatrix.sync.aligned.m8n8.x4.shared.b16 {%0,%1,%2,%3}, [%4];"
                 : "=r"(r[0]), "=r"(r[1]), "=r"(r[2]), "=r"(r[3]) : "r"(addr));
}
__device__ __forceinline__ void ldm_x4_trans(uint32_t* r, uint32_t addr) {
    asm volatile("ldmatrix.sync.aligned.m8n8.x4.trans.shared.b16 {%0,%1,%2,%3}, [%4];"
                 : "=r"(r[0]), "=r"(r[1]), "=r"(r[2]), "=r"(r[3]) : "r"(addr));
}
__device__ __forceinline__ void mma_f16(float* c, const uint32_t* a, const uint32_t* b) {
    asm volatile(
        "mma.sync.aligned.m16n8k16.row.col.f32.f16.f16.f32 "
        "{%0,%1,%2,%3}, {%4,%5,%6,%7}, {%8,%9}, {%0,%1,%2,%3};"
        : "+f"(c[0]), "+f"(c[1]), "+f"(c[2]), "+f"(c[3])
        : "r"(a[0]), "r"(a[1]), "r"(a[2]), "r"(a[3]), "r"(b[0]), "r"(b[1]));
}
__device__ __forceinline__ uint32_t pack2h(float a, float b) {
    __half2 h2 = __floats2half2_rn(a, b);
    return *reinterpret_cast<uint32_t*>(&h2);
}

// ---------------------------------------------------------------------------
// Fused pre-round: q_input + 4 weights -> fp16 (hi only), one launch.
// blocks [0,4096): q_in; [4096,8192): weights (1024 each).
// ---------------------------------------------------------------------------
__global__ __launch_bounds__(256) void split_all_kernel(
    const float* __restrict__ q_in,
    const float* __restrict__ WQ, const float* __restrict__ WK,
    const float* __restrict__ WV, const float* __restrict__ WO)
{
    const int blk = blockIdx.x;
    const float* src;
    __half* dst;
    int i;
    if (blk < 4096) {
        src = q_in; dst = g_qinh;
        i = blk * 256 + threadIdx.x;
    } else {
        const int w = (blk - 4096) >> 10;
        i = ((blk - 4096) & 1023) * 256 + threadIdx.x;
        switch (w) {
            case 0:  src = WQ; dst = g_wqh; break;
            case 1:  src = WK; dst = g_wkh; break;
            case 2:  src = WV; dst = g_wvh; break;
            default: src = WO; dst = g_woh; break;
        }
    }
    float4 v = reinterpret_cast<const float4*>(src)[i];
    reinterpret_cast<uint2*>(dst)[i] =
        make_uint2(pack2h(v.x, v.y), pack2h(v.z, v.w));
}

// ---------------------------------------------------------------------------
// Compaction scan: 1 block/batch, 1024 threads, 2 keys each.
// ---------------------------------------------------------------------------
__global__ __launch_bounds__(1024) void compact_scan_kernel(const int* __restrict__ mask)
{
    __shared__ int ssum[1024];
    const int b = blockIdx.x, t = threadIdx.x;
    const int* m = mask + (size_t)b * LK;
    const int f0 = (m[2 * t]     == 0) ? 1 : 0;
    const int f1 = (m[2 * t + 1] == 0) ? 1 : 0;
    ssum[t] = f0 + f1;
    __syncthreads();
    for (int off = 1; off < 1024; off <<= 1) {
        const int v = (t >= off) ? ssum[t - off] : 0;
        __syncthreads();
        ssum[t] += v;
        __syncthreads();
    }
    const int excl = ssum[t] - f0 - f1;
    if (f0) g_kidx[(size_t)b * LK + excl]      = 2 * t;
    if (f1) g_kidx[(size_t)b * LK + excl + f0] = 2 * t + 1;
    const int n = ssum[1023];
    if (t == 0) {
        g_nkv[b]  = n;
        g_npad[b] = (n + 127) & ~127;
    }
    g_biasc[(size_t)b * LK + 2 * t]     = (2 * t     < n) ? 0.0f : -1.0e30f;
    g_biasc[(size_t)b * LK + 2 * t + 1] = (2 * t + 1 < n) ? 0.0f : -1.0e30f;
}

// ---------------------------------------------------------------------------
// Fused gather + round: f32 kv rows -> compact fp16 (pads zeroed).
// ---------------------------------------------------------------------------
__global__ __launch_bounds__(256) void gather_split_kernel(const float* __restrict__ kv_in)
{
    const int b  = blockIdx.y;
    const int j0 = blockIdx.x * 8;
    const int n = g_nkv[b], npad = g_npad[b];
    if (j0 >= npad) return;
    const int tid = threadIdx.x;
    for (int i = tid; i < 8 * 256; i += 256) {
        const int r = i >> 8, c = i & 255;
        const int j = j0 + r;
        if (j >= npad) continue;
        uint2 uh = make_uint2(0, 0);
        if (j < n) {
            const int src = g_kidx[(size_t)b * LK + j];
            float4 v = reinterpret_cast<const float4*>(kv_in)
                           [((size_t)b * LK + src) * 256 + c];
            uh = make_uint2(pack2h(v.x, v.y), pack2h(v.z, v.w));
        }
        reinterpret_cast<uint2*>(g_ckinh)[((size_t)b * LK + j) * 256 + c] = uh;
    }
}

// ---------------------------------------------------------------------------
// GEMM core: pure fp16, 128x128 tile, BK=32, 256 thr, 2-stage cp.async,
// 2 CTAs/SM.  C = Ah * Bh.
// ---------------------------------------------------------------------------
#define G_STG 18944   // Ah 10240 + Bh 8704
#define GDSM  (2 * G_STG)

__device__ __forceinline__ void gemm_core(
    const __half* __restrict__ Ahg, const __half* __restrict__ Whg,
    int brow, int bcol, char* dsm, float acc[4][4][4])
{
    const uint32_t sb = smem_u32(dsm);
    const int tid  = threadIdx.x;
    const int warp = tid >> 5, lane = tid & 31;
    const int wm   = warp >> 2, wn = warp & 3;

#pragma unroll
    for (int mi = 0; mi < 4; mi++)
#pragma unroll
        for (int ni = 0; ni < 4; ni++)
#pragma unroll
            for (int r = 0; r < 4; r++) acc[mi][ni][r] = 0.0f;

    auto issue = [&](int kt, int s) {
        const int k0 = kt * 32;
        const uint32_t st = sb + s * G_STG;
#pragma unroll
        for (int i = 0; i < 2; i++) {
            const int idx = i * 256 + tid;
            const int r = idx >> 2, c = idx & 3;
            cp16(st + r * 80 + c * 16,
                 Ahg + (size_t)(brow + r) * D_MODEL + k0 + c * 8);
        }
#pragma unroll
        for (int i = 0; i < 2; i++) {
            const int idx = i * 256 + tid;
            const int r = idx >> 4, c = idx & 15;
            cp16(st + 10240 + r * 272 + c * 16,
                 Whg + (size_t)(k0 + r) * D_MODEL + bcol + c * 8);
        }
        cp_commit();
    };

    const int NK = D_MODEL / 32;
    issue(0, 0);
    for (int kt = 0; kt < NK; kt++) {
        const int s = kt & 1;
        if (kt + 1 < NK) {
            issue(kt + 1, s ^ 1);
            asm volatile("cp.async.wait_group 1;" ::: "memory");
        } else {
            asm volatile("cp.async.wait_group 0;" ::: "memory");
        }
        __syncthreads();

        const uint32_t ah = sb + s * G_STG;
        const uint32_t bh = ah + 10240;

#pragma unroll
        for (int ks = 0; ks < 2; ks++) {
            uint32_t afh[4][4], bfh[2][4];
#pragma unroll
            for (int mi = 0; mi < 4; mi++) {
                const int row = wm * 64 + mi * 16 + (lane & 15);
                const int col = ks * 16 + (lane >> 4) * 8;
                ldm_x4(afh[mi], ah + (uint32_t)(row * 40 + col) * 2);
            }
#pragma unroll
            for (int np = 0; np < 2; np++) {
                const int krow = ks * 16 + (lane & 15);
                const int ncol = wn * 32 + np * 16 + ((lane >> 4) & 1) * 8;
                ldm_x4_trans(bfh[np], bh + (uint32_t)(krow * 136 + ncol) * 2);
            }
#pragma unroll
            for (int mi = 0; mi < 4; mi++)
#pragma unroll
                for (int ni = 0; ni < 4; ni++)
                    mma_f16(acc[mi][ni], afh[mi], &bfh[ni >> 1][(ni & 1) * 2]);
        }
        __syncthreads();
    }
}

// ---------------------------------------------------------------------------
// Fused Q + K + V projection GEMM. grid (16, 96). fp16 hi-only outputs.
// ---------------------------------------------------------------------------
__global__ __launch_bounds__(256, 2) void gemm_qkv(
    const float* __restrict__ bQ, const float* __restrict__ bK,
    const float* __restrict__ bV)
{
    extern __shared__ __align__(16) char dsm[];

    const __half *Ahg, *Whg;
    const float* bias;
    __half* Ch;
    float scale;
    int brow, bx = blockIdx.x;

    if (blockIdx.y < 32) {
        if (bx >= 8) return;
        Ahg = g_qinh; Whg = g_wqh;
        bias = bQ; Ch = g_qh; scale = 0.125f;
        brow = blockIdx.y * 128;
    } else {
        brow = (blockIdx.y - 32) * 128;
        const int bb = brow / LK;
        if ((brow % LK) >= g_npad[bb]) return;
        Ahg = g_ckinh; scale = 1.0f;
        if (bx < 8) { Whg = g_wkh; bias = bK; Ch = g_kh; }
        else { bx -= 8; Whg = g_wvh; bias = bV; Ch = g_vh; }
    }
    const int bcol = bx * 128;

    float acc[4][4][4];
    gemm_core(Ahg, Whg, brow, bcol, dsm, acc);

    const int lane = threadIdx.x & 31, warp = threadIdx.x >> 5;
    const int wm = warp >> 2, wn = warp & 3;
    const int g = lane >> 2, t4 = lane & 3;
#pragma unroll
    for (int mi = 0; mi < 4; mi++) {
        const int row = brow + wm * 64 + mi * 16 + g;
#pragma unroll
        for (int ni = 0; ni < 4; ni++) {
            const int col = bcol + wn * 32 + ni * 8 + 2 * t4;
            const float b0 = bias[col], b1 = bias[col + 1];
            *reinterpret_cast<uint32_t*>(&Ch[(size_t)row * D_MODEL + col]) =
                pack2h((acc[mi][ni][0] + b0) * scale, (acc[mi][ni][1] + b1) * scale);
            *reinterpret_cast<uint32_t*>(&Ch[(size_t)(row + 8) * D_MODEL + col]) =
                pack2h((acc[mi][ni][2] + b0) * scale, (acc[mi][ni][3] + b1) * scale);
        }
    }
}

// Output projection: fp32 out to d_out.
__global__ __launch_bounds__(256, 2) void gemm_o(
    const float* __restrict__ bO, float* __restrict__ C)
{
    extern __shared__ __align__(16) char dsm[];
    const int brow = blockIdx.y * 128;
    const int bcol = blockIdx.x * 128;

    float acc[4][4][4];
    gemm_core(g_ah, g_woh, brow, bcol, dsm, acc);

    const int lane = threadIdx.x & 31, warp = threadIdx.x >> 5;
    const int wm = warp >> 2, wn = warp & 3;
    const int g = lane >> 2, t4 = lane & 3;
#pragma unroll
    for (int mi = 0; mi < 4; mi++) {
        const int row = brow + wm * 64 + mi * 16 + g;
#pragma unroll
        for (int ni = 0; ni < 4; ni++) {
            const int col = bcol + wn * 32 + ni * 8 + 2 * t4;
            const float b0 = bO[col], b1 = bO[col + 1];
            *reinterpret_cast<float2*>(C + (size_t)row * D_MODEL + col) =
                make_float2(acc[mi][ni][0] + b0, acc[mi][ni][1] + b1);
            *reinterpret_cast<float2*>(C + (size_t)(row + 8) * D_MODEL + col) =
                make_float2(acc[mi][ni][2] + b0, acc[mi][ni][3] + b1);
        }
    }
}

// ---------------------------------------------------------------------------
// Pure-fp16 tensor-core flash attention: S = Qh*Kh, O = Ph*Vh.
// QT=64, 128 threads / 4 warps, 3 CTAs/SM, 2-stage cp.async pipeline.
// ---------------------------------------------------------------------------
#define A_TS   9216
#define A_STG  (2 * A_TS)
#define A_BOFF (2 * A_STG)
#define A_DSM  (A_BOFF + 512)

__global__ __launch_bounds__(128, 3) void attn_mma()
{
    extern __shared__ __align__(16) char dsm[];
    const uint32_t sb = smem_u32(dsm);

    const int tid  = threadIdx.x;
    const int warp = tid >> 5, lane = tid & 31;
    const int g    = lane >> 2, t4 = lane & 3;
    const int q0   = blockIdx.x * 64;
    const int h    = blockIdx.y;
    const int b    = blockIdx.z;
    const int NK   = g_npad[b] / 64;

    // ---- Q fragments via stage-0 area ----
    uint32_t qfh[4][4];
    {
        const size_t qbase = ((size_t)b * LQ + q0) * D_MODEL + h * D_H;
#pragma unroll
        for (int i = 0; i < 4; i++) {
            const int idx = i * 128 + tid;
            const int r = idx >> 3, c = idx & 7;
            *reinterpret_cast<uint4*>(dsm + r * 144 + c * 16) =
                *reinterpret_cast<const uint4*>(g_qh + qbase + (size_t)r * D_MODEL + c * 8);
        }
        __syncthreads();
        const int rbase = warp * 16;
#pragma unroll
        for (int s = 0; s < 4; s++) {
            const uint32_t off =
                (uint32_t)((rbase + (lane & 15)) * 72 + (lane >> 4) * 8 + s * 16) * 2;
            ldm_x4(qfh[s], sb + off);
        }
        __syncthreads();
    }

    auto issue = [&](int kt, int s) {
        const size_t kvbase = ((size_t)b * LK + kt * 64) * D_MODEL + h * D_H;
        const uint32_t st = sb + s * A_STG;
#pragma unroll
        for (int i = 0; i < 8; i++) {
            const int tile = i >> 2;
            const int idx = (i & 3) * 128 + tid;
            const int r = idx >> 3, c = idx & 7;
            const size_t go = kvbase + (size_t)r * D_MODEL + c * 8;
            cp16(st + tile * A_TS + r * 144 + c * 16,
                 (tile == 0 ? g_kh : g_vh) + go);
        }
        if (tid < 16)
            cp16(sb + A_BOFF + s * 256 + tid * 16,
                 g_biasc + (size_t)b * LK + kt * 64 + tid * 4);
        cp_commit();
    };

    float m0 = -1.0e30f, m1 = -1.0e30f, l0 = 0.0f, l1 = 0.0f;
    float o[8][4];
#pragma unroll
    for (int j = 0; j < 8; j++)
#pragma unroll
        for (int r = 0; r < 4; r++) o[j][r] = 0.0f;

    issue(0, 0);
    for (int kt = 0; kt < NK; kt++) {
        const int st = kt & 1;
        if (kt + 1 < NK) {
            issue(kt + 1, st ^ 1);
            asm volatile("cp.async.wait_group 1;" ::: "memory");
        } else {
            asm volatile("cp.async.wait_group 0;" ::: "memory");
        }
        __syncthreads();

        const uint32_t khb = sb + st * A_STG;
        const uint32_t vhb = khb + A_TS;
        const float* bias_s = reinterpret_cast<const float*>(dsm + A_BOFF + st * 256);

        // ---- S = Qh Kh^T ----
        float s[8][4];
#pragma unroll
        for (int j = 0; j < 8; j++)
#pragma unroll
            for (int r = 0; r < 4; r++) s[j][r] = 0.0f;

#pragma unroll
        for (int ks = 0; ks < 4; ks++) {
#pragma unroll
            for (int jp2 = 0; jp2 < 2; jp2++) {
                uint32_t kh4[2][4];
#pragma unroll
                for (int q = 0; q < 2; q++) {
                    const int jp = jp2 * 2 + q;
                    const int row = jp * 16 + ((lane >> 4) & 1) * 8 + (lane & 7);
                    const int col = ks * 16 + ((lane >> 3) & 1) * 8;
                    ldm_x4(kh4[q], khb + (uint32_t)(row * 72 + col) * 2);
                }
#pragma unroll
                for (int q = 0; q < 2; q++) {
                    const int j0 = (jp2 * 2 + q) * 2;
                    mma_f16(s[j0],     qfh[ks], kh4[q]);
                    mma_f16(s[j0 + 1], qfh[ks], kh4[q] + 2);
                }
            }
        }

        // ---- pad bias + online softmax ----
        float mx0 = -1.0e30f, mx1 = -1.0e30f;
#pragma unroll
        for (int j = 0; j < 8; j++) {
            const float b0 = bias_s[j * 8 + 2 * t4];
            const float b1 = bias_s[j * 8 + 2 * t4 + 1];
            s[j][0] += b0; s[j][1] += b1;
            s[j][2] += b0; s[j][3] += b1;
            mx0 = fmaxf(mx0, fmaxf(s[j][0], s[j][1]));
            mx1 = fmaxf(mx1, fmaxf(s[j][2], s[j][3]));
        }
        mx0 = fmaxf(mx0, __shfl_xor_sync(0xffffffffu, mx0, 1));
        mx0 = fmaxf(mx0, __shfl_xor_sync(0xffffffffu, mx0, 2));
        mx1 = fmaxf(mx1, __shfl_xor_sync(0xffffffffu, mx1, 1));
        mx1 = fmaxf(mx1, __shfl_xor_sync(0xffffffffu, mx1, 2));

        const float m0n = fmaxf(m0, mx0), m1n = fmaxf(m1, mx1);
        const float c0 = __expf(m0 - m0n), c1 = __expf(m1 - m1n);
        m0 = m0n; m1 = m1n;

        float sum0 = 0.0f, sum1 = 0.0f;
#pragma unroll
        for (int j = 0; j < 8; j++) {
            s[j][0] = __expf(s[j][0] - m0n);
            s[j][1] = __expf(s[j][1] - m0n);
            s[j][2] = __expf(s[j][2] - m1n);
            s[j][3] = __expf(s[j][3] - m1n);
            sum0 += s[j][0] + s[j][1];
            sum1 += s[j][2] + s[j][3];
        }
        sum0 += __shfl_xor_sync(0xffffffffu, sum0, 1);
        sum0 += __shfl_xor_sync(0xffffffffu, sum0, 2);
        sum1 += __shfl_xor_sync(0xffffffffu, sum1, 1);
        sum1 += __shfl_xor_sync(0xffffffffu, sum1, 2);
        l0 = l0 * c0 + sum0;
        l1 = l1 * c1 + sum1;

#pragma unroll
        for (int j = 0; j < 8; j++) {
            o[j][0] *= c0; o[j][1] *= c0;
            o[j][2] *= c1; o[j][3] *= c1;
        }

        // ---- O += Ph Vh ----
#pragma unroll
        for (int ks = 0; ks < 4; ks++) {
            uint32_t pah[4];
            pah[0] = pack2h(s[2 * ks][0],     s[2 * ks][1]);
            pah[1] = pack2h(s[2 * ks][2],     s[2 * ks][3]);
            pah[2] = pack2h(s[2 * ks + 1][0], s[2 * ks + 1][1]);
            pah[3] = pack2h(s[2 * ks + 1][2], s[2 * ks + 1][3]);
#pragma unroll
            for (int jp2 = 0; jp2 < 2; jp2++) {
                uint32_t vh4[2][4];
#pragma unroll
                for (int q = 0; q < 2; q++) {
                    const int jp = jp2 * 2 + q;
                    const int row = ks * 16 + (lane & 15);
                    const int col = jp * 16 + ((lane >> 4) & 1) * 8;
                    ldm_x4_trans(vh4[q], vhb + (uint32_t)(row * 72 + col) * 2);
                }
#pragma unroll
                for (int q = 0; q < 2; q++) {
                    const int j0 = (jp2 * 2 + q) * 2;
                    mma_f16(o[j0],     pah, vh4[q]);
                    mma_f16(o[j0 + 1], pah, vh4[q] + 2);
                }
            }
        }
        __syncthreads();
    }

    // ---- normalize + write fp16 output ----
    const float li0 = 1.0f / l0, li1 = 1.0f / l1;
    const int row0 = q0 + warp * 16 + g;
    const size_t base0 = ((size_t)b * LQ + row0) * D_MODEL + h * D_H;
    const size_t base1 = base0 + (size_t)8 * D_MODEL;
#pragma unroll
    for (int j = 0; j < 8; j++) {
        const int col = j * 8 + 2 * t4;
        *reinterpret_cast<uint32_t*>(&g_ah[base0 + col]) =
            pack2h(o[j][0] * li0, o[j][1] * li0);
        *reinterpret_cast<uint32_t*>(&g_ah[base1 + col]) =
            pack2h(o[j][2] * li1, o[j][3] * li1);
    }
}

// ---------------------------------------------------------------------------
// Launch
// ---------------------------------------------------------------------------
extern "C" void kernel_launch(void* const* d_in, const int* in_sizes, int n_in,
                              void* d_out, int out_size)
{
    const float* q_in  = (const float*)d_in[0];
    const float* kv_in = (const float*)d_in[1];
    const int*   mask  = (const int*)  d_in[2];
    const float* W_Q   = (const float*)d_in[3];
    const float* b_Q   = (const float*)d_in[4];
    const float* W_K   = (const float*)d_in[5];
    const float* b_K   = (const float*)d_in[6];
    const float* W_V   = (const float*)d_in[7];
    const float* b_V   = (const float*)d_in[8];
    const float* W_O   = (const float*)d_in[9];
    const float* b_O   = (const float*)d_in[10];

    cudaFuncSetAttribute(gemm_qkv, cudaFuncAttributeMaxDynamicSharedMemorySize, GDSM);
    cudaFuncSetAttribute(gemm_o,   cudaFuncAttributeMaxDynamicSharedMemorySize, GDSM);
    cudaFuncSetAttribute(attn_mma, cudaFuncAttributeMaxDynamicSharedMemorySize, A_DSM);

    // ---- preprocessing: rounds + compaction ----
    split_all_kernel<<<8192, 256>>>(q_in, W_Q, W_K, W_V, W_O);
    compact_scan_kernel<<<BATCH, 1024>>>(mask);
    gather_split_kernel<<<dim3(LK / 8, BATCH), 256>>>(kv_in);

    // ---- fused Q/K/V projections ----
    gemm_qkv<<<dim3(16, 96), 256, GDSM>>>(b_Q, b_K, b_V);

    // ---- attention over compacted keys ----
    attn_mma<<<dim3(LQ / 64, N_HEAD, BATCH), 128, A_DSM>>>();

    // ---- output projection ----
    gemm_o<<<dim3(8, 32), 256, GDSM>>>(b_O, (float*)d_out);
}